// round 1
// baseline (speedup 1.0000x reference)
#include <cuda_runtime.h>
#include <math.h>

#define N_TOK 8192
#define D_IN  512
#define HID   256
#define C_OUT 256
#define NCHUNK 16
#define ROWS_PER_CHUNK (N_TOK / NCHUNK)

// Scratch (static __device__ — allocation-free per harness rules)
__device__ float g_h [N_TOK * HID];
__device__ float g_q [N_TOK * HID];
__device__ float g_k [N_TOK * HID];
__device__ float g_v [N_TOK * HID];     // becomes v' = v*(1-a)/Z
__device__ float g_h2[N_TOK * HID];
__device__ float g_S [(size_t)N_TOK * N_TOK];   // scores, then exp(scores - m_col)
__device__ float g_pm[NCHUNK * N_TOK];
__device__ float g_pZ[NCHUNK * N_TOK];
__device__ float g_m [N_TOK];
__device__ float g_Z [N_TOK];

// ---------------------------------------------------------------------------
// Tiled SGEMM: C[M,N] = A[M,K] @ (TRANS_B ? B[N,K]^T : B[K,N]) (+ epilogue)
// MODE 0: C = acc + bias[col]
// MODE 1: C = acc * scale
// MODE 2: C = (*aptr) * hres + acc        (gated residual; v' carries (1-a)/Z)
// BM=BN=128, BK=16, 256 threads, 8x8 per thread. All dims multiples of tiles.
// ---------------------------------------------------------------------------
template <int MODE, bool TRANS_B>
__global__ __launch_bounds__(256) void sgemm_kernel(
    const float* __restrict__ A, const float* __restrict__ B,
    float* __restrict__ C, int M, int N, int K,
    const float* __restrict__ bias, float scale,
    const float* __restrict__ hres, const float* __restrict__ aptr)
{
    __shared__ float As[16][128];
    __shared__ float Bs[16][128];

    const int tid  = threadIdx.x;
    const int row0 = blockIdx.y * 128;
    const int col0 = blockIdx.x * 128;
    const int trow = tid >> 4;   // 0..15
    const int tcol = tid & 15;   // 0..15

    float acc[8][8];
#pragma unroll
    for (int i = 0; i < 8; i++)
#pragma unroll
        for (int j = 0; j < 8; j++) acc[i][j] = 0.0f;

    for (int k0 = 0; k0 < K; k0 += 16) {
        // Load A tile 128x16 (transposed into As[k][m]); 512 float4, 2/thread
#pragma unroll
        for (int l = 0; l < 2; l++) {
            int f  = tid + l * 256;
            int ar = f >> 2;
            int ac = (f & 3) << 2;
            float4 va = *reinterpret_cast<const float4*>(
                &A[(size_t)(row0 + ar) * K + k0 + ac]);
            As[ac + 0][ar] = va.x; As[ac + 1][ar] = va.y;
            As[ac + 2][ar] = va.z; As[ac + 3][ar] = va.w;
        }
        // Load B tile into Bs[k][n]
        if (!TRANS_B) {
#pragma unroll
            for (int l = 0; l < 2; l++) {
                int f  = tid + l * 256;
                int br = f >> 5;          // k 0..15
                int bc = (f & 31) << 2;   // n 0..124
                float4 vb = *reinterpret_cast<const float4*>(
                    &B[(size_t)(k0 + br) * N + col0 + bc]);
                *reinterpret_cast<float4*>(&Bs[br][bc]) = vb;
            }
        } else {
#pragma unroll
            for (int l = 0; l < 2; l++) {
                int f  = tid + l * 256;
                int br = f >> 2;          // n 0..127
                int bc = (f & 3) << 2;    // k 0,4,8,12
                float4 vb = *reinterpret_cast<const float4*>(
                    &B[(size_t)(col0 + br) * K + k0 + bc]);
                Bs[bc + 0][br] = vb.x; Bs[bc + 1][br] = vb.y;
                Bs[bc + 2][br] = vb.z; Bs[bc + 3][br] = vb.w;
            }
        }
        __syncthreads();

#pragma unroll
        for (int kk = 0; kk < 16; kk++) {
            float ar[8], br[8];
            *reinterpret_cast<float4*>(&ar[0]) =
                *reinterpret_cast<const float4*>(&As[kk][trow * 8 + 0]);
            *reinterpret_cast<float4*>(&ar[4]) =
                *reinterpret_cast<const float4*>(&As[kk][trow * 8 + 4]);
            *reinterpret_cast<float4*>(&br[0]) =
                *reinterpret_cast<const float4*>(&Bs[kk][tcol * 8 + 0]);
            *reinterpret_cast<float4*>(&br[4]) =
                *reinterpret_cast<const float4*>(&Bs[kk][tcol * 8 + 4]);
#pragma unroll
            for (int i = 0; i < 8; i++)
#pragma unroll
                for (int j = 0; j < 8; j++) acc[i][j] += ar[i] * br[j];
        }
        __syncthreads();
    }

    const int crow = row0 + trow * 8;
    const int ccol = col0 + tcol * 8;
    float aval = 0.0f;
    if (MODE == 2) aval = *aptr;

#pragma unroll
    for (int i = 0; i < 8; i++) {
        size_t base = (size_t)(crow + i) * N + ccol;
#pragma unroll
        for (int jv = 0; jv < 8; jv += 4) {
            float4 o;
            if (MODE == 0) {
                float4 bb = *reinterpret_cast<const float4*>(&bias[ccol + jv]);
                o.x = acc[i][jv + 0] + bb.x; o.y = acc[i][jv + 1] + bb.y;
                o.z = acc[i][jv + 2] + bb.z; o.w = acc[i][jv + 3] + bb.w;
            } else if (MODE == 1) {
                o.x = acc[i][jv + 0] * scale; o.y = acc[i][jv + 1] * scale;
                o.z = acc[i][jv + 2] * scale; o.w = acc[i][jv + 3] * scale;
            } else {
                float4 hh = *reinterpret_cast<const float4*>(&hres[base + jv]);
                o.x = aval * hh.x + acc[i][jv + 0];
                o.y = aval * hh.y + acc[i][jv + 1];
                o.z = aval * hh.z + acc[i][jv + 2];
                o.w = aval * hh.w + acc[i][jv + 3];
            }
            *reinterpret_cast<float4*>(&C[base + jv]) = o;
        }
    }
}

// ---------------------------------------------------------------------------
// Column softmax stats, pass 1: per (row-chunk, column) online max + sum-exp
// grid (N_TOK/256, NCHUNK), 256 threads; thread owns one column j, coalesced.
// ---------------------------------------------------------------------------
__global__ __launch_bounds__(256) void colstats_partial(const float* __restrict__ S)
{
    int j  = blockIdx.x * 256 + threadIdx.x;
    int i0 = blockIdx.y * ROWS_PER_CHUNK;
    float mx = -INFINITY, s = 0.0f;
    for (int i = i0; i < i0 + ROWS_PER_CHUNK; i++) {
        float x  = S[(size_t)i * N_TOK + j];
        float mn = fmaxf(mx, x);
        s = s * expf(mx - mn) + expf(x - mn);
        mx = mn;
    }
    g_pm[blockIdx.y * N_TOK + j] = mx;
    g_pZ[blockIdx.y * N_TOK + j] = s;
}

__global__ __launch_bounds__(256) void colstats_combine()
{
    int j = blockIdx.x * 256 + threadIdx.x;
    float mx = -INFINITY, s = 0.0f;
#pragma unroll
    for (int c = 0; c < NCHUNK; c++) {
        float mc = g_pm[c * N_TOK + j];
        float zc = g_pZ[c * N_TOK + j];
        float mn = fmaxf(mx, mc);
        s  = s * expf(mx - mn) + zc * expf(mc - mn);
        mx = mn;
    }
    g_m[j] = mx;
    g_Z[j] = s;
}

// S[i,j] <- exp(S[i,j] - m[j]); float4 over contiguous columns
__global__ __launch_bounds__(256) void exp_kernel(float* __restrict__ S)
{
    size_t t    = (size_t)blockIdx.x * 256 + threadIdx.x;
    size_t base = t * 4;
    int col = (int)(base & (N_TOK - 1));
    float4 x  = *reinterpret_cast<float4*>(&S[base]);
    float4 mm = *reinterpret_cast<const float4*>(&g_m[col]);
    x.x = expf(x.x - mm.x); x.y = expf(x.y - mm.y);
    x.z = expf(x.z - mm.z); x.w = expf(x.w - mm.w);
    *reinterpret_cast<float4*>(&S[base]) = x;
}

// v[j,:] *= (1-a)/Z[j]
__global__ __launch_bounds__(256) void vprime_kernel(const float* __restrict__ aptr)
{
    size_t t    = (size_t)blockIdx.x * 256 + threadIdx.x;
    size_t base = t * 4;
    int j = (int)(base / HID);
    float sc = (1.0f - *aptr) / g_Z[j];
    float4 x = *reinterpret_cast<float4*>(&g_v[base]);
    x.x *= sc; x.y *= sc; x.z *= sc; x.w *= sc;
    *reinterpret_cast<float4*>(&g_v[base]) = x;
}

// ---------------------------------------------------------------------------
extern "C" void kernel_launch(void* const* d_in, const int* in_sizes, int n_in,
                              void* d_out, int out_size)
{
    const float* x  = (const float*)d_in[0];
    const float* W1 = (const float*)d_in[1];
    const float* b1 = (const float*)d_in[2];
    const float* Wq = (const float*)d_in[3];
    const float* bq = (const float*)d_in[4];
    const float* Wk = (const float*)d_in[5];
    const float* bk = (const float*)d_in[6];
    const float* Wv = (const float*)d_in[7];
    const float* bv = (const float*)d_in[8];
    const float* a  = (const float*)d_in[9];
    const float* W2 = (const float*)d_in[10];
    const float* b2 = (const float*)d_in[11];
    float* out = (float*)d_out;

    float *h, *q, *k, *v, *h2, *S;
    cudaGetSymbolAddress((void**)&h,  g_h);
    cudaGetSymbolAddress((void**)&q,  g_q);
    cudaGetSymbolAddress((void**)&k,  g_k);
    cudaGetSymbolAddress((void**)&v,  g_v);
    cudaGetSymbolAddress((void**)&h2, g_h2);
    cudaGetSymbolAddress((void**)&S,  g_S);

    const float scale = 0.0625f; // 1/sqrt(256)
    dim3 blk(256);

    // 1) h = x @ W1 + b1
    sgemm_kernel<0, false><<<dim3(HID / 128, N_TOK / 128), blk>>>(
        x, W1, h, N_TOK, HID, D_IN, b1, 0.f, nullptr, nullptr);
    // 2) q,k,v
    sgemm_kernel<0, false><<<dim3(HID / 128, N_TOK / 128), blk>>>(
        h, Wq, q, N_TOK, HID, HID, bq, 0.f, nullptr, nullptr);
    sgemm_kernel<0, false><<<dim3(HID / 128, N_TOK / 128), blk>>>(
        h, Wk, k, N_TOK, HID, HID, bk, 0.f, nullptr, nullptr);
    sgemm_kernel<0, false><<<dim3(HID / 128, N_TOK / 128), blk>>>(
        h, Wv, v, N_TOK, HID, HID, bv, 0.f, nullptr, nullptr);
    // 3) S = (q @ k^T) * scale
    sgemm_kernel<1, true><<<dim3(N_TOK / 128, N_TOK / 128), blk>>>(
        q, k, S, N_TOK, N_TOK, HID, nullptr, scale, nullptr, nullptr);
    // 4) column softmax stats
    colstats_partial<<<dim3(N_TOK / 256, NCHUNK), blk>>>(S);
    colstats_combine<<<N_TOK / 256, blk>>>();
    // 5) S <- exp(S - m[col])
    exp_kernel<<<(unsigned)((size_t)N_TOK * N_TOK / 4 / 256), blk>>>(S);
    // 6) v' = v * (1-a)/Z
    vprime_kernel<<<(N_TOK * HID / 4) / 256, blk>>>(a);
    // 7) h2 = a*h + E @ v'
    sgemm_kernel<2, false><<<dim3(HID / 128, N_TOK / 128), blk>>>(
        S, v, h2, N_TOK, HID, N_TOK, nullptr, 0.f, h, a);
    // 8) out = h2 @ W2 + b2
    sgemm_kernel<0, false><<<dim3(C_OUT / 128, N_TOK / 128), blk>>>(
        h2, W2, out, N_TOK, C_OUT, HID, b2, 0.f, nullptr, nullptr);

    (void)in_sizes; (void)n_in; (void)out_size;
}

// round 3
// speedup vs baseline: 2.4196x; 2.4196x over previous
#include <cuda_runtime.h>
#include <stdint.h>
#include <math.h>

#define N_TOK 8192
#define D_IN  512
#define HID   256
#define C_OUT 256
#define NCHUNK 16
#define ROWS_PER_CHUNK (N_TOK / NCHUNK)

// Scratch (static __device__ — allocation-free per harness rules)
__device__ float g_h [N_TOK * HID];
__device__ float g_q [N_TOK * HID];
__device__ float g_k [N_TOK * HID];
__device__ float g_v [N_TOK * HID];     // becomes v' = v*(1-a)/Z
__device__ float g_h2[N_TOK * HID];
__device__ float g_S [(size_t)N_TOK * N_TOK];   // raw scaled scores
__device__ float g_pm[NCHUNK * N_TOK];
__device__ float g_pZ[NCHUNK * N_TOK];
__device__ float g_m [N_TOK];
__device__ float g_Z [N_TOK];

__device__ __forceinline__ uint32_t f2tf32(float f) {
    uint32_t u;
    asm("cvt.rna.tf32.f32 %0, %1;" : "=r"(u) : "f"(f));
    return u;
}

// ---------------------------------------------------------------------------
// tf32 tensor-core GEMM: C[M,N] = A[M,K] @ (TRANS_B ? B[N,K]^T : B[K,N])
// MODE 0: += bias[col]   MODE 1: *= scale   MODE 2: C = (*aptr)*hres + acc
// EXP_A: A elements become exp(A - mcol[k]) while staging to SMEM.
// BM=BN=128, BK=32, 256 threads (8 warps, 2x4), warp tile 64x32, m16n8k8.
// SMEM strides chosen bank-conflict-free for both STS.128 and fragment LDS.
// ---------------------------------------------------------------------------
template <int MODE, bool TRANS_B, bool EXP_A>
__global__ __launch_bounds__(256, 2) void mma_gemm(
    const float* __restrict__ A, const float* __restrict__ B,
    float* __restrict__ C, int M, int N, int K,
    const float* __restrict__ bias, float scale,
    const float* __restrict__ hres, const float* __restrict__ aptr,
    const float* __restrict__ mcol)
{
    __shared__ uint32_t Asm[128 * 36];                        // [m][k], stride 36
    __shared__ uint32_t Bsm[TRANS_B ? (128 * 36) : (32 * 136)];

    const int tid  = threadIdx.x;
    const int row0 = blockIdx.y * 128;
    const int col0 = blockIdx.x * 128;
    const int lane = tid & 31;
    const int wid  = tid >> 5;
    const int wm   = wid >> 2;          // 0..1 -> 64 rows
    const int wn   = wid & 3;           // 0..3 -> 32 cols
    const int g    = lane >> 2;         // 0..7
    const int tg   = lane & 3;          // 0..3

    const int a_r = tid >> 3;           // 0..31 (+32*l)
    const int a_c = (tid & 7) * 4;      // k offset 0..28
    const int b_k = tid >> 5;           // 0..7  (+8*l)
    const int b_n = (tid & 31) * 4;     // n offset 0..124

    float acc[4][4][4];
#pragma unroll
    for (int i = 0; i < 4; i++)
#pragma unroll
        for (int j = 0; j < 4; j++)
#pragma unroll
            for (int r = 0; r < 4; r++) acc[i][j][r] = 0.0f;

    for (int k0 = 0; k0 < K; k0 += 32) {
        // --- stage A tile [128 x 32] into Asm[m*36 + k] ---
#pragma unroll
        for (int l = 0; l < 4; l++) {
            int r = a_r + 32 * l;
            float4 v = *reinterpret_cast<const float4*>(
                &A[(size_t)(row0 + r) * K + k0 + a_c]);
            if (EXP_A) {
                float4 mv = *reinterpret_cast<const float4*>(&mcol[k0 + a_c]);
                v.x = __expf(v.x - mv.x); v.y = __expf(v.y - mv.y);
                v.z = __expf(v.z - mv.z); v.w = __expf(v.w - mv.w);
            }
            uint4 u = make_uint4(f2tf32(v.x), f2tf32(v.y), f2tf32(v.z), f2tf32(v.w));
            *reinterpret_cast<uint4*>(&Asm[r * 36 + a_c]) = u;
        }
        // --- stage B tile ---
        if (TRANS_B) {
            // B[N][K] row-major -> Bsm[n*36 + k] (direct copy)
#pragma unroll
            for (int l = 0; l < 4; l++) {
                int r = a_r + 32 * l;
                float4 v = *reinterpret_cast<const float4*>(
                    &B[(size_t)(col0 + r) * K + k0 + a_c]);
                uint4 u = make_uint4(f2tf32(v.x), f2tf32(v.y), f2tf32(v.z), f2tf32(v.w));
                *reinterpret_cast<uint4*>(&Bsm[r * 36 + a_c]) = u;
            }
        } else {
            // B[K][N] row-major -> Bsm[k*136 + n] (direct copy)
#pragma unroll
            for (int l = 0; l < 4; l++) {
                int kk = b_k + 8 * l;
                float4 v = *reinterpret_cast<const float4*>(
                    &B[(size_t)(k0 + kk) * N + col0 + b_n]);
                uint4 u = make_uint4(f2tf32(v.x), f2tf32(v.y), f2tf32(v.z), f2tf32(v.w));
                *reinterpret_cast<uint4*>(&Bsm[kk * 136 + b_n]) = u;
            }
        }
        __syncthreads();

        // --- compute: 4 k8 steps ---
#pragma unroll
        for (int ks = 0; ks < 4; ks++) {
            const int k8 = ks * 8;
            uint32_t af[4][4], bf[4][2];
#pragma unroll
            for (int mt = 0; mt < 4; mt++) {
                int mrow = wm * 64 + mt * 16 + g;
                af[mt][0] = Asm[(mrow    ) * 36 + k8 + tg    ];
                af[mt][1] = Asm[(mrow + 8) * 36 + k8 + tg    ];
                af[mt][2] = Asm[(mrow    ) * 36 + k8 + tg + 4];
                af[mt][3] = Asm[(mrow + 8) * 36 + k8 + tg + 4];
            }
#pragma unroll
            for (int nt = 0; nt < 4; nt++) {
                int ncol = wn * 32 + nt * 8 + g;
                if (TRANS_B) {
                    bf[nt][0] = Bsm[ncol * 36 + k8 + tg    ];
                    bf[nt][1] = Bsm[ncol * 36 + k8 + tg + 4];
                } else {
                    bf[nt][0] = Bsm[(k8 + tg    ) * 136 + ncol];
                    bf[nt][1] = Bsm[(k8 + tg + 4) * 136 + ncol];
                }
            }
#pragma unroll
            for (int mt = 0; mt < 4; mt++)
#pragma unroll
                for (int nt = 0; nt < 4; nt++) {
                    asm volatile(
                        "mma.sync.aligned.m16n8k8.row.col.f32.tf32.tf32.f32 "
                        "{%0,%1,%2,%3}, {%4,%5,%6,%7}, {%8,%9}, {%0,%1,%2,%3};"
                        : "+f"(acc[mt][nt][0]), "+f"(acc[mt][nt][1]),
                          "+f"(acc[mt][nt][2]), "+f"(acc[mt][nt][3])
                        : "r"(af[mt][0]), "r"(af[mt][1]),
                          "r"(af[mt][2]), "r"(af[mt][3]),
                          "r"(bf[nt][0]), "r"(bf[nt][1]));
                }
        }
        __syncthreads();
    }

    // --- epilogue ---
    float aval = 0.0f;
    if (MODE == 2) aval = *aptr;
    const int rbase = row0 + wm * 64;
    const int cbase = col0 + wn * 32;
#pragma unroll
    for (int mt = 0; mt < 4; mt++)
#pragma unroll
        for (int nt = 0; nt < 4; nt++)
#pragma unroll
            for (int hh = 0; hh < 2; hh++) {
                int r = rbase + mt * 16 + g + 8 * hh;
                int c = cbase + nt * 8 + 2 * tg;
                float o0 = acc[mt][nt][2 * hh + 0];
                float o1 = acc[mt][nt][2 * hh + 1];
                size_t base = (size_t)r * N + c;
                if (MODE == 0) {
                    o0 += bias[c]; o1 += bias[c + 1];
                } else if (MODE == 1) {
                    o0 *= scale; o1 *= scale;
                } else {
                    o0 = aval * hres[base]     + o0;
                    o1 = aval * hres[base + 1] + o1;
                }
                float2 o = make_float2(o0, o1);
                *reinterpret_cast<float2*>(&C[base]) = o;
            }
}

// ---------------------------------------------------------------------------
// Column softmax stats (softmax over rows/dim 0): per-column max + sum-exp
// ---------------------------------------------------------------------------
__global__ __launch_bounds__(256) void colstats_partial(const float* __restrict__ S)
{
    int j  = blockIdx.x * 256 + threadIdx.x;
    int i0 = blockIdx.y * ROWS_PER_CHUNK;
    float mx = -INFINITY, s = 0.0f;
    for (int i = i0; i < i0 + ROWS_PER_CHUNK; i++) {
        float x  = S[(size_t)i * N_TOK + j];
        float mn = fmaxf(mx, x);
        s = s * expf(mx - mn) + expf(x - mn);
        mx = mn;
    }
    g_pm[blockIdx.y * N_TOK + j] = mx;
    g_pZ[blockIdx.y * N_TOK + j] = s;
}

__global__ __launch_bounds__(256) void colstats_combine()
{
    int j = blockIdx.x * 256 + threadIdx.x;
    float mx = -INFINITY, s = 0.0f;
#pragma unroll
    for (int c = 0; c < NCHUNK; c++) {
        float mc = g_pm[c * N_TOK + j];
        float zc = g_pZ[c * N_TOK + j];
        float mn = fmaxf(mx, mc);
        s  = s * expf(mx - mn) + zc * expf(mc - mn);
        mx = mn;
    }
    g_m[j] = mx;
    g_Z[j] = s;
}

// v[j,:] *= (1-a)/Z[j]
__global__ __launch_bounds__(256) void vprime_kernel(const float* __restrict__ aptr)
{
    size_t t    = (size_t)blockIdx.x * 256 + threadIdx.x;
    size_t base = t * 4;
    int j = (int)(base / HID);
    float sc = (1.0f - *aptr) / g_Z[j];
    float4 x = *reinterpret_cast<float4*>(&g_v[base]);
    x.x *= sc; x.y *= sc; x.z *= sc; x.w *= sc;
    *reinterpret_cast<float4*>(&g_v[base]) = x;
}

// ---------------------------------------------------------------------------
extern "C" void kernel_launch(void* const* d_in, const int* in_sizes, int n_in,
                              void* d_out, int out_size)
{
    const float* x  = (const float*)d_in[0];
    const float* W1 = (const float*)d_in[1];
    const float* b1 = (const float*)d_in[2];
    const float* Wq = (const float*)d_in[3];
    const float* bq = (const float*)d_in[4];
    const float* Wk = (const float*)d_in[5];
    const float* bk = (const float*)d_in[6];
    const float* Wv = (const float*)d_in[7];
    const float* bv = (const float*)d_in[8];
    const float* a  = (const float*)d_in[9];
    const float* W2 = (const float*)d_in[10];
    const float* b2 = (const float*)d_in[11];
    float* out = (float*)d_out;

    float *h, *q, *k, *v, *h2, *S, *m;
    cudaGetSymbolAddress((void**)&h,  g_h);
    cudaGetSymbolAddress((void**)&q,  g_q);
    cudaGetSymbolAddress((void**)&k,  g_k);
    cudaGetSymbolAddress((void**)&v,  g_v);
    cudaGetSymbolAddress((void**)&h2, g_h2);
    cudaGetSymbolAddress((void**)&S,  g_S);
    cudaGetSymbolAddress((void**)&m,  g_m);

    const float scale = 0.0625f; // 1/sqrt(256)
    dim3 blk(256);

    // 1) h = x @ W1 + b1
    mma_gemm<0, false, false><<<dim3(HID / 128, N_TOK / 128), blk>>>(
        x, W1, h, N_TOK, HID, D_IN, b1, 0.f, nullptr, nullptr, nullptr);
    // 2) q,k,v
    mma_gemm<0, false, false><<<dim3(HID / 128, N_TOK / 128), blk>>>(
        h, Wq, q, N_TOK, HID, HID, bq, 0.f, nullptr, nullptr, nullptr);
    mma_gemm<0, false, false><<<dim3(HID / 128, N_TOK / 128), blk>>>(
        h, Wk, k, N_TOK, HID, HID, bk, 0.f, nullptr, nullptr, nullptr);
    mma_gemm<0, false, false><<<dim3(HID / 128, N_TOK / 128), blk>>>(
        h, Wv, v, N_TOK, HID, HID, bv, 0.f, nullptr, nullptr, nullptr);
    // 3) S = (q @ k^T) * scale
    mma_gemm<1, true, false><<<dim3(N_TOK / 128, N_TOK / 128), blk>>>(
        q, k, S, N_TOK, N_TOK, HID, nullptr, scale, nullptr, nullptr, nullptr);
    // 4) column softmax stats
    colstats_partial<<<dim3(N_TOK / 256, NCHUNK), blk>>>(S);
    colstats_combine<<<N_TOK / 256, blk>>>();
    // 5) v' = v * (1-a)/Z
    vprime_kernel<<<(N_TOK * HID / 4) / 256, blk>>>(a);
    // 6) h2 = a*h + exp(S - m[col]) @ v'   (exp fused into A staging)
    mma_gemm<2, false, true><<<dim3(HID / 128, N_TOK / 128), blk>>>(
        S, v, h2, N_TOK, HID, N_TOK, nullptr, 0.f, h, a, m);
    // 7) out = h2 @ W2 + b2
    mma_gemm<0, false, false><<<dim3(C_OUT / 128, N_TOK / 128), blk>>>(
        h2, W2, out, N_TOK, C_OUT, HID, b2, 0.f, nullptr, nullptr, nullptr);

    (void)in_sizes; (void)n_in; (void)out_size;
}

// round 4
// speedup vs baseline: 2.5201x; 1.0415x over previous
#include <cuda_runtime.h>
#include <stdint.h>
#include <math.h>

#define N_TOK 8192
#define D_IN  512
#define HID   256
#define C_OUT 256
#define NCHUNK 16
#define ROWS_PER_CHUNK (N_TOK / NCHUNK)

// Scratch (static __device__ — allocation-free per harness rules)
__device__ float g_h [N_TOK * HID];
__device__ float g_q [N_TOK * HID];
__device__ float g_k [N_TOK * HID];
__device__ float g_v [N_TOK * HID];     // becomes v' = v*(1-a)/Z
__device__ float g_h2[N_TOK * HID];
__device__ float g_S [(size_t)N_TOK * N_TOK];   // raw scaled scores
__device__ float g_pm[NCHUNK * N_TOK];
__device__ float g_pZ[NCHUNK * N_TOK];
__device__ float g_m [N_TOK];
__device__ float g_Z [N_TOK];

__device__ __forceinline__ uint32_t f2tf32(float f) {
    uint32_t u;
    asm("cvt.rna.tf32.f32 %0, %1;" : "=r"(u) : "f"(f));
    return u;
}

// ---------------------------------------------------------------------------
// tf32 tensor-core GEMM, double-buffered software pipeline.
// C[M,N] = A[M,K] @ (TRANS_B ? B[N,K]^T : B[K,N])
// MODE 0: += bias[col]   MODE 1: *= scale   MODE 2: C = (*aptr)*hres + acc
// EXP_A: A elements become exp(A - mcol[k]) while staging to SMEM.
// BM=BN=128, BK=32, 256 threads (8 warps, 2x4), warp tile 64x32, m16n8k8.
// ---------------------------------------------------------------------------
template <int MODE, bool TRANS_B, bool EXP_A>
__global__ __launch_bounds__(256) void mma_gemm(
    const float* __restrict__ A, const float* __restrict__ B,
    float* __restrict__ C, int M, int N, int K,
    const float* __restrict__ bias, float scale,
    const float* __restrict__ hres, const float* __restrict__ aptr,
    const float* __restrict__ mcol)
{
    __shared__ uint32_t Asm[2][128 * 36];                     // [m][k], stride 36
    __shared__ uint32_t Bsm[2][TRANS_B ? (128 * 36) : (32 * 136)];

    const int tid  = threadIdx.x;
    const int row0 = blockIdx.y * 128;
    const int col0 = blockIdx.x * 128;
    const int lane = tid & 31;
    const int wid  = tid >> 5;
    const int wm   = wid >> 2;          // 0..1 -> 64 rows
    const int wn   = wid & 3;           // 0..3 -> 32 cols
    const int g    = lane >> 2;         // 0..7
    const int tg   = lane & 3;          // 0..3

    const int a_r = tid >> 3;           // 0..31 (+32*l)
    const int a_c = (tid & 7) * 4;      // k offset 0..28
    const int b_k = tid >> 5;           // 0..7  (+8*l)
    const int b_n = (tid & 31) * 4;     // n offset 0..124

    float acc[4][4][4];
#pragma unroll
    for (int i = 0; i < 4; i++)
#pragma unroll
        for (int j = 0; j < 4; j++)
#pragma unroll
            for (int r = 0; r < 4; r++) acc[i][j][r] = 0.0f;

    float4 aR[4], bR[4];

    // ---- global -> regs for tile at k0 ----
    auto ldg_tile = [&](int k0) {
#pragma unroll
        for (int l = 0; l < 4; l++) {
            int r = a_r + 32 * l;
            float4 v = *reinterpret_cast<const float4*>(
                &A[(size_t)(row0 + r) * K + k0 + a_c]);
            if (EXP_A) {
                float4 mv = *reinterpret_cast<const float4*>(&mcol[k0 + a_c]);
                v.x = __expf(v.x - mv.x); v.y = __expf(v.y - mv.y);
                v.z = __expf(v.z - mv.z); v.w = __expf(v.w - mv.w);
            }
            aR[l] = v;
        }
        if (TRANS_B) {
#pragma unroll
            for (int l = 0; l < 4; l++) {
                int r = a_r + 32 * l;
                bR[l] = *reinterpret_cast<const float4*>(
                    &B[(size_t)(col0 + r) * K + k0 + a_c]);
            }
        } else {
#pragma unroll
            for (int l = 0; l < 4; l++) {
                int kk = b_k + 8 * l;
                bR[l] = *reinterpret_cast<const float4*>(
                    &B[(size_t)(k0 + kk) * N + col0 + b_n]);
            }
        }
    };

    // ---- regs -> SMEM buffer s ----
    auto sts_tile = [&](int s) {
#pragma unroll
        for (int l = 0; l < 4; l++) {
            int r = a_r + 32 * l;
            *reinterpret_cast<uint4*>(&Asm[s][r * 36 + a_c]) =
                make_uint4(f2tf32(aR[l].x), f2tf32(aR[l].y),
                           f2tf32(aR[l].z), f2tf32(aR[l].w));
        }
        if (TRANS_B) {
#pragma unroll
            for (int l = 0; l < 4; l++) {
                int r = a_r + 32 * l;
                *reinterpret_cast<uint4*>(&Bsm[s][r * 36 + a_c]) =
                    make_uint4(f2tf32(bR[l].x), f2tf32(bR[l].y),
                               f2tf32(bR[l].z), f2tf32(bR[l].w));
            }
        } else {
#pragma unroll
            for (int l = 0; l < 4; l++) {
                int kk = b_k + 8 * l;
                *reinterpret_cast<uint4*>(&Bsm[s][kk * 136 + b_n]) =
                    make_uint4(f2tf32(bR[l].x), f2tf32(bR[l].y),
                               f2tf32(bR[l].z), f2tf32(bR[l].w));
            }
        }
    };

    // ---- MMA on SMEM buffer s ----
    auto compute = [&](int s) {
#pragma unroll
        for (int ks = 0; ks < 4; ks++) {
            const int k8 = ks * 8;
            uint32_t af[4][4], bf[4][2];
#pragma unroll
            for (int mt = 0; mt < 4; mt++) {
                int mrow = wm * 64 + mt * 16 + g;
                af[mt][0] = Asm[s][(mrow    ) * 36 + k8 + tg    ];
                af[mt][1] = Asm[s][(mrow + 8) * 36 + k8 + tg    ];
                af[mt][2] = Asm[s][(mrow    ) * 36 + k8 + tg + 4];
                af[mt][3] = Asm[s][(mrow + 8) * 36 + k8 + tg + 4];
            }
#pragma unroll
            for (int nt = 0; nt < 4; nt++) {
                int ncol = wn * 32 + nt * 8 + g;
                if (TRANS_B) {
                    bf[nt][0] = Bsm[s][ncol * 36 + k8 + tg    ];
                    bf[nt][1] = Bsm[s][ncol * 36 + k8 + tg + 4];
                } else {
                    bf[nt][0] = Bsm[s][(k8 + tg    ) * 136 + ncol];
                    bf[nt][1] = Bsm[s][(k8 + tg + 4) * 136 + ncol];
                }
            }
#pragma unroll
            for (int mt = 0; mt < 4; mt++)
#pragma unroll
                for (int nt = 0; nt < 4; nt++) {
                    asm volatile(
                        "mma.sync.aligned.m16n8k8.row.col.f32.tf32.tf32.f32 "
                        "{%0,%1,%2,%3}, {%4,%5,%6,%7}, {%8,%9}, {%0,%1,%2,%3};"
                        : "+f"(acc[mt][nt][0]), "+f"(acc[mt][nt][1]),
                          "+f"(acc[mt][nt][2]), "+f"(acc[mt][nt][3])
                        : "r"(af[mt][0]), "r"(af[mt][1]),
                          "r"(af[mt][2]), "r"(af[mt][3]),
                          "r"(bf[nt][0]), "r"(bf[nt][1]));
                }
        }
    };

    // ---- pipelined mainloop ----
    ldg_tile(0);
    sts_tile(0);
    __syncthreads();

    const int niter = K / 32;
    for (int it = 0; it < niter; it++) {
        int cur = it & 1;
        if (it + 1 < niter) ldg_tile((it + 1) * 32);   // LDGs issue before MMAs
        compute(cur);
        if (it + 1 < niter) {
            sts_tile(cur ^ 1);
            __syncthreads();
        }
    }

    // --- epilogue ---
    float aval = 0.0f;
    if (MODE == 2) aval = *aptr;
    const int rbase = row0 + wm * 64;
    const int cbase = col0 + wn * 32;
#pragma unroll
    for (int mt = 0; mt < 4; mt++)
#pragma unroll
        for (int nt = 0; nt < 4; nt++)
#pragma unroll
            for (int hh = 0; hh < 2; hh++) {
                int r = rbase + mt * 16 + g + 8 * hh;
                int c = cbase + nt * 8 + 2 * tg;
                float o0 = acc[mt][nt][2 * hh + 0];
                float o1 = acc[mt][nt][2 * hh + 1];
                size_t base = (size_t)r * N + c;
                if (MODE == 0) {
                    o0 += bias[c]; o1 += bias[c + 1];
                } else if (MODE == 1) {
                    o0 *= scale; o1 *= scale;
                } else {
                    o0 = aval * hres[base]     + o0;
                    o1 = aval * hres[base + 1] + o1;
                }
                *reinterpret_cast<float2*>(&C[base]) = make_float2(o0, o1);
            }
}

// ---------------------------------------------------------------------------
// Column softmax stats (softmax over rows/dim 0): per-column max + sum-exp
// ---------------------------------------------------------------------------
__global__ __launch_bounds__(256) void colstats_partial(const float* __restrict__ S)
{
    int j  = blockIdx.x * 256 + threadIdx.x;
    int i0 = blockIdx.y * ROWS_PER_CHUNK;
    float mx = -INFINITY, s = 0.0f;
    for (int i = i0; i < i0 + ROWS_PER_CHUNK; i++) {
        float x  = S[(size_t)i * N_TOK + j];
        float mn = fmaxf(mx, x);
        s = s * __expf(mx - mn) + __expf(x - mn);
        mx = mn;
    }
    g_pm[blockIdx.y * N_TOK + j] = mx;
    g_pZ[blockIdx.y * N_TOK + j] = s;
}

__global__ __launch_bounds__(256) void colstats_combine()
{
    int j = blockIdx.x * 256 + threadIdx.x;
    float mx = -INFINITY, s = 0.0f;
#pragma unroll
    for (int c = 0; c < NCHUNK; c++) {
        float mc = g_pm[c * N_TOK + j];
        float zc = g_pZ[c * N_TOK + j];
        float mn = fmaxf(mx, mc);
        s  = s * __expf(mx - mn) + zc * __expf(mc - mn);
        mx = mn;
    }
    g_m[j] = mx;
    g_Z[j] = s;
}

// v[j,:] *= (1-a)/Z[j]
__global__ __launch_bounds__(256) void vprime_kernel(const float* __restrict__ aptr)
{
    size_t t    = (size_t)blockIdx.x * 256 + threadIdx.x;
    size_t base = t * 4;
    int j = (int)(base / HID);
    float sc = (1.0f - *aptr) / g_Z[j];
    float4 x = *reinterpret_cast<float4*>(&g_v[base]);
    x.x *= sc; x.y *= sc; x.z *= sc; x.w *= sc;
    *reinterpret_cast<float4*>(&g_v[base]) = x;
}

// ---------------------------------------------------------------------------
extern "C" void kernel_launch(void* const* d_in, const int* in_sizes, int n_in,
                              void* d_out, int out_size)
{
    const float* x  = (const float*)d_in[0];
    const float* W1 = (const float*)d_in[1];
    const float* b1 = (const float*)d_in[2];
    const float* Wq = (const float*)d_in[3];
    const float* bq = (const float*)d_in[4];
    const float* Wk = (const float*)d_in[5];
    const float* bk = (const float*)d_in[6];
    const float* Wv = (const float*)d_in[7];
    const float* bv = (const float*)d_in[8];
    const float* a  = (const float*)d_in[9];
    const float* W2 = (const float*)d_in[10];
    const float* b2 = (const float*)d_in[11];
    float* out = (float*)d_out;

    float *h, *q, *k, *v, *h2, *S, *m;
    cudaGetSymbolAddress((void**)&h,  g_h);
    cudaGetSymbolAddress((void**)&q,  g_q);
    cudaGetSymbolAddress((void**)&k,  g_k);
    cudaGetSymbolAddress((void**)&v,  g_v);
    cudaGetSymbolAddress((void**)&h2, g_h2);
    cudaGetSymbolAddress((void**)&S,  g_S);
    cudaGetSymbolAddress((void**)&m,  g_m);

    const float scale = 0.0625f; // 1/sqrt(256)
    dim3 blk(256);

    // 1) h = x @ W1 + b1
    mma_gemm<0, false, false><<<dim3(HID / 128, N_TOK / 128), blk>>>(
        x, W1, h, N_TOK, HID, D_IN, b1, 0.f, nullptr, nullptr, nullptr);
    // 2) q,k,v
    mma_gemm<0, false, false><<<dim3(HID / 128, N_TOK / 128), blk>>>(
        h, Wq, q, N_TOK, HID, HID, bq, 0.f, nullptr, nullptr, nullptr);
    mma_gemm<0, false, false><<<dim3(HID / 128, N_TOK / 128), blk>>>(
        h, Wk, k, N_TOK, HID, HID, bk, 0.f, nullptr, nullptr, nullptr);
    mma_gemm<0, false, false><<<dim3(HID / 128, N_TOK / 128), blk>>>(
        h, Wv, v, N_TOK, HID, HID, bv, 0.f, nullptr, nullptr, nullptr);
    // 3) S = (q @ k^T) * scale
    mma_gemm<1, true, false><<<dim3(N_TOK / 128, N_TOK / 128), blk>>>(
        q, k, S, N_TOK, N_TOK, HID, nullptr, scale, nullptr, nullptr, nullptr);
    // 4) column softmax stats
    colstats_partial<<<dim3(N_TOK / 256, NCHUNK), blk>>>(S);
    colstats_combine<<<N_TOK / 256, blk>>>();
    // 5) v' = v * (1-a)/Z
    vprime_kernel<<<(N_TOK * HID / 4) / 256, blk>>>(a);
    // 6) h2 = a*h + exp(S - m[col]) @ v'   (exp fused into A staging)
    mma_gemm<2, false, true><<<dim3(HID / 128, N_TOK / 128), blk>>>(
        S, v, h2, N_TOK, HID, N_TOK, nullptr, 0.f, h, a, m);
    // 7) out = h2 @ W2 + b2
    mma_gemm<0, false, false><<<dim3(C_OUT / 128, N_TOK / 128), blk>>>(
        h2, W2, out, N_TOK, C_OUT, HID, b2, 0.f, nullptr, nullptr, nullptr);

    (void)in_sizes; (void)n_in; (void)out_size;
}

// round 5
// speedup vs baseline: 2.5240x; 1.0016x over previous
#include <cuda_runtime.h>
#include <stdint.h>
#include <math.h>

#define N_TOK 8192
#define D_IN  512
#define HID   256
#define C_OUT 256
#define NCHUNK 16
#define ROWS_PER_CHUNK (N_TOK / NCHUNK)

// Scratch (static __device__ — allocation-free per harness rules)
__device__ float g_h [N_TOK * HID];
__device__ float g_q [N_TOK * HID];
__device__ float g_k [N_TOK * HID];
__device__ float g_v [N_TOK * HID];     // becomes v' = v*(1-a)/Z
__device__ float g_h2[N_TOK * HID];
__device__ float g_S [(size_t)N_TOK * N_TOK];   // raw scaled scores
__device__ float g_pm[NCHUNK * N_TOK];
__device__ float g_pZ[NCHUNK * N_TOK];
__device__ float g_m [N_TOK];
__device__ float g_Z [N_TOK];

__device__ __forceinline__ uint32_t f2tf32(float f) {
    uint32_t u;
    asm("cvt.rna.tf32.f32 %0, %1;" : "=r"(u) : "f"(f));
    return u;
}

// ---------------------------------------------------------------------------
// tf32 tensor-core GEMM, double-buffered software pipeline.
// C[M,N] = A[M,K] @ (TRANS_B ? B[N,K]^T : B[K,N])
// MODE 0: += bias[col]   MODE 1: *= scale   MODE 2: C = (*aptr)*hres + acc
// EXP_A: A elements become exp(A - mcol[k]) while staging to SMEM.
// BM=BN=128, BK=32, 256 threads (8 warps, 2x4), warp tile 64x32, m16n8k8.
// ---------------------------------------------------------------------------
template <int MODE, bool TRANS_B, bool EXP_A>
__global__ __launch_bounds__(256) void mma_gemm(
    const float* __restrict__ A, const float* __restrict__ B,
    float* __restrict__ C, int M, int N, int K,
    const float* __restrict__ bias, float scale,
    const float* __restrict__ hres, const float* __restrict__ aptr,
    const float* __restrict__ mcol)
{
    __shared__ uint32_t Asm[2][128 * 36];                     // [m][k], stride 36
    __shared__ uint32_t Bsm[2][TRANS_B ? (128 * 36) : (32 * 136)];

    const int tid  = threadIdx.x;
    const int row0 = blockIdx.y * 128;
    const int col0 = blockIdx.x * 128;
    const int lane = tid & 31;
    const int wid  = tid >> 5;
    const int wm   = wid >> 2;          // 0..1 -> 64 rows
    const int wn   = wid & 3;           // 0..3 -> 32 cols
    const int g    = lane >> 2;         // 0..7
    const int tg   = lane & 3;          // 0..3

    const int a_r = tid >> 3;           // 0..31 (+32*l)
    const int a_c = (tid & 7) * 4;      // k offset 0..28
    const int b_k = tid >> 5;           // 0..7  (+8*l)
    const int b_n = (tid & 31) * 4;     // n offset 0..124

    float acc[4][4][4];
#pragma unroll
    for (int i = 0; i < 4; i++)
#pragma unroll
        for (int j = 0; j < 4; j++)
#pragma unroll
            for (int r = 0; r < 4; r++) acc[i][j][r] = 0.0f;

    float4 aR[4], bR[4];

    // ---- global -> regs for tile at k0 ----
    auto ldg_tile = [&](int k0) {
#pragma unroll
        for (int l = 0; l < 4; l++) {
            int r = a_r + 32 * l;
            float4 v = *reinterpret_cast<const float4*>(
                &A[(size_t)(row0 + r) * K + k0 + a_c]);
            if (EXP_A) {
                float4 mv = *reinterpret_cast<const float4*>(&mcol[k0 + a_c]);
                v.x = __expf(v.x - mv.x); v.y = __expf(v.y - mv.y);
                v.z = __expf(v.z - mv.z); v.w = __expf(v.w - mv.w);
            }
            aR[l] = v;
        }
        if (TRANS_B) {
#pragma unroll
            for (int l = 0; l < 4; l++) {
                int r = a_r + 32 * l;
                bR[l] = *reinterpret_cast<const float4*>(
                    &B[(size_t)(col0 + r) * K + k0 + a_c]);
            }
        } else {
#pragma unroll
            for (int l = 0; l < 4; l++) {
                int kk = b_k + 8 * l;
                bR[l] = *reinterpret_cast<const float4*>(
                    &B[(size_t)(k0 + kk) * N + col0 + b_n]);
            }
        }
    };

    // ---- regs -> SMEM buffer s ----
    auto sts_tile = [&](int s) {
#pragma unroll
        for (int l = 0; l < 4; l++) {
            int r = a_r + 32 * l;
            *reinterpret_cast<uint4*>(&Asm[s][r * 36 + a_c]) =
                make_uint4(f2tf32(aR[l].x), f2tf32(aR[l].y),
                           f2tf32(aR[l].z), f2tf32(aR[l].w));
        }
        if (TRANS_B) {
#pragma unroll
            for (int l = 0; l < 4; l++) {
                int r = a_r + 32 * l;
                *reinterpret_cast<uint4*>(&Bsm[s][r * 36 + a_c]) =
                    make_uint4(f2tf32(bR[l].x), f2tf32(bR[l].y),
                               f2tf32(bR[l].z), f2tf32(bR[l].w));
            }
        } else {
#pragma unroll
            for (int l = 0; l < 4; l++) {
                int kk = b_k + 8 * l;
                *reinterpret_cast<uint4*>(&Bsm[s][kk * 136 + b_n]) =
                    make_uint4(f2tf32(bR[l].x), f2tf32(bR[l].y),
                               f2tf32(bR[l].z), f2tf32(bR[l].w));
            }
        }
    };

    // ---- MMA on SMEM buffer s ----
    auto compute = [&](int s) {
#pragma unroll
        for (int ks = 0; ks < 4; ks++) {
            const int k8 = ks * 8;
            uint32_t af[4][4], bf[4][2];
#pragma unroll
            for (int mt = 0; mt < 4; mt++) {
                int mrow = wm * 64 + mt * 16 + g;
                af[mt][0] = Asm[s][(mrow    ) * 36 + k8 + tg    ];
                af[mt][1] = Asm[s][(mrow + 8) * 36 + k8 + tg    ];
                af[mt][2] = Asm[s][(mrow    ) * 36 + k8 + tg + 4];
                af[mt][3] = Asm[s][(mrow + 8) * 36 + k8 + tg + 4];
            }
#pragma unroll
            for (int nt = 0; nt < 4; nt++) {
                int ncol = wn * 32 + nt * 8 + g;
                if (TRANS_B) {
                    bf[nt][0] = Bsm[s][ncol * 36 + k8 + tg    ];
                    bf[nt][1] = Bsm[s][ncol * 36 + k8 + tg + 4];
                } else {
                    bf[nt][0] = Bsm[s][(k8 + tg    ) * 136 + ncol];
                    bf[nt][1] = Bsm[s][(k8 + tg + 4) * 136 + ncol];
                }
            }
#pragma unroll
            for (int mt = 0; mt < 4; mt++)
#pragma unroll
                for (int nt = 0; nt < 4; nt++) {
                    asm volatile(
                        "mma.sync.aligned.m16n8k8.row.col.f32.tf32.tf32.f32 "
                        "{%0,%1,%2,%3}, {%4,%5,%6,%7}, {%8,%9}, {%0,%1,%2,%3};"
                        : "+f"(acc[mt][nt][0]), "+f"(acc[mt][nt][1]),
                          "+f"(acc[mt][nt][2]), "+f"(acc[mt][nt][3])
                        : "r"(af[mt][0]), "r"(af[mt][1]),
                          "r"(af[mt][2]), "r"(af[mt][3]),
                          "r"(bf[nt][0]), "r"(bf[nt][1]));
                }
        }
    };

    // ---- pipelined mainloop ----
    ldg_tile(0);
    sts_tile(0);
    __syncthreads();

    const int niter = K / 32;
    for (int it = 0; it < niter; it++) {
        int cur = it & 1;
        if (it + 1 < niter) ldg_tile((it + 1) * 32);   // LDGs issue before MMAs
        compute(cur);
        if (it + 1 < niter) {
            sts_tile(cur ^ 1);
            __syncthreads();
        }
    }

    // --- epilogue ---
    float aval = 0.0f;
    if (MODE == 2) aval = *aptr;
    const int rbase = row0 + wm * 64;
    const int cbase = col0 + wn * 32;
#pragma unroll
    for (int mt = 0; mt < 4; mt++)
#pragma unroll
        for (int nt = 0; nt < 4; nt++)
#pragma unroll
            for (int hh = 0; hh < 2; hh++) {
                int r = rbase + mt * 16 + g + 8 * hh;
                int c = cbase + nt * 8 + 2 * tg;
                float o0 = acc[mt][nt][2 * hh + 0];
                float o1 = acc[mt][nt][2 * hh + 1];
                size_t base = (size_t)r * N + c;
                if (MODE == 0) {
                    o0 += bias[c]; o1 += bias[c + 1];
                } else if (MODE == 1) {
                    o0 *= scale; o1 *= scale;
                } else {
                    o0 = aval * hres[base]     + o0;
                    o1 = aval * hres[base + 1] + o1;
                }
                *reinterpret_cast<float2*>(&C[base]) = make_float2(o0, o1);
            }
}

// ---------------------------------------------------------------------------
// Column softmax stats (softmax over rows/dim 0): per-column max + sum-exp
// ---------------------------------------------------------------------------
__global__ __launch_bounds__(256) void colstats_partial(const float* __restrict__ S)
{
    int j  = blockIdx.x * 256 + threadIdx.x;
    int i0 = blockIdx.y * ROWS_PER_CHUNK;
    float mx = -INFINITY, s = 0.0f;
    for (int i = i0; i < i0 + ROWS_PER_CHUNK; i++) {
        float x  = S[(size_t)i * N_TOK + j];
        float mn = fmaxf(mx, x);
        s = s * __expf(mx - mn) + __expf(x - mn);
        mx = mn;
    }
    g_pm[blockIdx.y * N_TOK + j] = mx;
    g_pZ[blockIdx.y * N_TOK + j] = s;
}

__global__ __launch_bounds__(256) void colstats_combine()
{
    int j = blockIdx.x * 256 + threadIdx.x;
    float mx = -INFINITY, s = 0.0f;
#pragma unroll
    for (int c = 0; c < NCHUNK; c++) {
        float mc = g_pm[c * N_TOK + j];
        float zc = g_pZ[c * N_TOK + j];
        float mn = fmaxf(mx, mc);
        s  = s * __expf(mx - mn) + zc * __expf(mc - mn);
        mx = mn;
    }
    g_m[j] = mx;
    g_Z[j] = s;
}

// v[j,:] *= (1-a)/Z[j]
__global__ __launch_bounds__(256) void vprime_kernel(const float* __restrict__ aptr)
{
    size_t t    = (size_t)blockIdx.x * 256 + threadIdx.x;
    size_t base = t * 4;
    int j = (int)(base / HID);
    float sc = (1.0f - *aptr) / g_Z[j];
    float4 x = *reinterpret_cast<float4*>(&g_v[base]);
    x.x *= sc; x.y *= sc; x.z *= sc; x.w *= sc;
    *reinterpret_cast<float4*>(&g_v[base]) = x;
}

// ---------------------------------------------------------------------------
extern "C" void kernel_launch(void* const* d_in, const int* in_sizes, int n_in,
                              void* d_out, int out_size)
{
    const float* x  = (const float*)d_in[0];
    const float* W1 = (const float*)d_in[1];
    const float* b1 = (const float*)d_in[2];
    const float* Wq = (const float*)d_in[3];
    const float* bq = (const float*)d_in[4];
    const float* Wk = (const float*)d_in[5];
    const float* bk = (const float*)d_in[6];
    const float* Wv = (const float*)d_in[7];
    const float* bv = (const float*)d_in[8];
    const float* a  = (const float*)d_in[9];
    const float* W2 = (const float*)d_in[10];
    const float* b2 = (const float*)d_in[11];
    float* out = (float*)d_out;

    float *h, *q, *k, *v, *h2, *S, *m;
    cudaGetSymbolAddress((void**)&h,  g_h);
    cudaGetSymbolAddress((void**)&q,  g_q);
    cudaGetSymbolAddress((void**)&k,  g_k);
    cudaGetSymbolAddress((void**)&v,  g_v);
    cudaGetSymbolAddress((void**)&h2, g_h2);
    cudaGetSymbolAddress((void**)&S,  g_S);
    cudaGetSymbolAddress((void**)&m,  g_m);

    const float scale = 0.0625f; // 1/sqrt(256)
    dim3 blk(256);

    // 1) h = x @ W1 + b1
    mma_gemm<0, false, false><<<dim3(HID / 128, N_TOK / 128), blk>>>(
        x, W1, h, N_TOK, HID, D_IN, b1, 0.f, nullptr, nullptr, nullptr);
    // 2) q,k,v
    mma_gemm<0, false, false><<<dim3(HID / 128, N_TOK / 128), blk>>>(
        h, Wq, q, N_TOK, HID, HID, bq, 0.f, nullptr, nullptr, nullptr);
    mma_gemm<0, false, false><<<dim3(HID / 128, N_TOK / 128), blk>>>(
        h, Wk, k, N_TOK, HID, HID, bk, 0.f, nullptr, nullptr, nullptr);
    mma_gemm<0, false, false><<<dim3(HID / 128, N_TOK / 128), blk>>>(
        h, Wv, v, N_TOK, HID, HID, bv, 0.f, nullptr, nullptr, nullptr);
    // 3) S = (q @ k^T) * scale
    mma_gemm<1, true, false><<<dim3(N_TOK / 128, N_TOK / 128), blk>>>(
        q, k, S, N_TOK, N_TOK, HID, nullptr, scale, nullptr, nullptr, nullptr);
    // 4) column softmax stats
    colstats_partial<<<dim3(N_TOK / 256, NCHUNK), blk>>>(S);
    colstats_combine<<<N_TOK / 256, blk>>>();
    // 5) v' = v * (1-a)/Z
    vprime_kernel<<<(N_TOK * HID / 4) / 256, blk>>>(a);
    // 6) h2 = a*h + exp(S - m[col]) @ v'   (exp fused into A staging)
    mma_gemm<2, false, true><<<dim3(HID / 128, N_TOK / 128), blk>>>(
        S, v, h2, N_TOK, HID, N_TOK, nullptr, 0.f, h, a, m);
    // 7) out = h2 @ W2 + b2
    mma_gemm<0, false, false><<<dim3(C_OUT / 128, N_TOK / 128), blk>>>(
        h2, W2, out, N_TOK, C_OUT, HID, b2, 0.f, nullptr, nullptr, nullptr);

    (void)in_sizes; (void)n_in; (void)out_size;
}

// round 8
// speedup vs baseline: 3.5316x; 1.3992x over previous
#include <cuda_runtime.h>
#include <cuda_fp16.h>
#include <stdint.h>
#include <math.h>

#define N_TOK 8192
#define D_IN  512
#define HID   256
#define C_OUT 256
#define NCHUNK 16
#define ROWS_PER_CHUNK (N_TOK / NCHUNK)

// ---- scratch (static __device__, allocation-free) ----
__device__ float g_h [N_TOK * HID];
__device__ float g_q [N_TOK * HID];
__device__ float g_k [N_TOK * HID];
__device__ float g_v [N_TOK * HID];
__device__ float g_h2[N_TOK * HID];
__device__ float g_S [(size_t)N_TOK * N_TOK];
__device__ float g_pm[NCHUNK * N_TOK];
__device__ float g_pZ[NCHUNK * N_TOK];
__device__ float g_LZ[N_TOK];           // m + ln Z per column
__device__ float g_W1t[HID * D_IN];
__device__ float g_Wqt[HID * HID];
__device__ float g_Wkt[HID * HID];
__device__ float g_Wvt[HID * HID];
__device__ float g_W2t[C_OUT * HID];
__device__ float g_vT [HID * N_TOK];    // (v*(1-a))^T : [256][8192]

__device__ __forceinline__ uint32_t smem_u32(const void* p) {
    uint32_t a;
    asm("{ .reg .u64 t; cvta.to.shared.u64 t, %1; cvt.u32.u64 %0, t; }"
        : "=r"(a) : "l"(p));
    return a;
}

__device__ __forceinline__ uint2 pack_f4(float4 v) {
    __half2 h0 = __floats2half2_rn(v.x, v.y);
    __half2 h1 = __floats2half2_rn(v.z, v.w);
    uint2 u;
    u.x = *reinterpret_cast<uint32_t*>(&h0);
    u.y = *reinterpret_cast<uint32_t*>(&h1);
    return u;
}

#define LDSM_X4(r0, r1, r2, r3, addr) \
    asm volatile("ldmatrix.sync.aligned.m8n8.x4.shared.b16 {%0,%1,%2,%3}, [%4];" \
        : "=r"(r0), "=r"(r1), "=r"(r2), "=r"(r3) : "r"(addr))

#define MMA_16816(c, a, b) \
    asm volatile("mma.sync.aligned.m16n8k16.row.col.f32.f16.f16.f32 " \
        "{%0,%1,%2,%3}, {%4,%5,%6,%7}, {%8,%9}, {%0,%1,%2,%3};" \
        : "+f"((c)[0]), "+f"((c)[1]), "+f"((c)[2]), "+f"((c)[3]) \
        : "r"((a)[0]), "r"((a)[1]), "r"((a)[2]), "r"((a)[3]), \
          "r"((b)[0]), "r"((b)[1]))

// SMEM row stride: 40 halves = 80B (= 20 words; gcd(20,32)=4 -> 8 distinct row
// banks per LDSM phase -> conflict-free ldmatrix).
#define SSTR 40

// ---------------------------------------------------------------------------
// fp16 tensor-core NT GEMM: C[M,N] = A[M,K] @ Bt[N,K]^T  (f32 in/out, f32 accum)
// MODE 0: += bias[col]   MODE 1: *= scale   MODE 2: C = (*aptr)*hres + acc
// EXP_A: A elements become exp(A - lzcol[k]) while prefetching.
// CTA 128x128, BK=32, 256 thr (8 warps 2x4), warp 64x32, double-buffered.
// ---------------------------------------------------------------------------
template <int MODE, bool EXP_A>
__global__ __launch_bounds__(256, 2) void hmma_gemm(
    const float* __restrict__ A, const float* __restrict__ Bt,
    float* __restrict__ C, int M, int N, int K,
    const float* __restrict__ bias, float scale,
    const float* __restrict__ hres, const float* __restrict__ aptr,
    const float* __restrict__ lzcol)
{
    __shared__ __align__(16) __half Asm[2][128 * SSTR];
    __shared__ __align__(16) __half Bsm[2][128 * SSTR];

    const int tid  = threadIdx.x;
    const int lane = tid & 31;
    const int wid  = tid >> 5;
    const int wm   = wid >> 2;          // 0..1  (64 rows)
    const int wn   = wid & 3;           // 0..3  (32 cols)
    const int row0 = blockIdx.y * 128;
    const int col0 = blockIdx.x * 128;

    const int a_r = tid >> 3;           // 0..31 (+32*l)
    const int a_c = (tid & 7) * 4;      // k offset 0..28

    float acc[4][4][4];
#pragma unroll
    for (int i = 0; i < 4; i++)
#pragma unroll
        for (int j = 0; j < 4; j++)
#pragma unroll
            for (int r = 0; r < 4; r++) acc[i][j][r] = 0.0f;

    uint2 aR[4], bR[4];                 // prefetched, already half2-packed

    auto ldg_tile = [&](int k0) {
#pragma unroll
        for (int l = 0; l < 4; l++) {
            int r = a_r + 32 * l;
            float4 v = *reinterpret_cast<const float4*>(
                &A[(size_t)(row0 + r) * K + k0 + a_c]);
            if (EXP_A) {
                float4 mv = *reinterpret_cast<const float4*>(&lzcol[k0 + a_c]);
                v.x = __expf(v.x - mv.x); v.y = __expf(v.y - mv.y);
                v.z = __expf(v.z - mv.z); v.w = __expf(v.w - mv.w);
            }
            aR[l] = pack_f4(v);
            bR[l] = pack_f4(*reinterpret_cast<const float4*>(
                &Bt[(size_t)(col0 + r) * K + k0 + a_c]));
        }
    };

    auto sts_tile = [&](int s) {
#pragma unroll
        for (int l = 0; l < 4; l++) {
            int r = a_r + 32 * l;
            *reinterpret_cast<uint2*>(&Asm[s][r * SSTR + a_c]) = aR[l];
            *reinterpret_cast<uint2*>(&Bsm[s][r * SSTR + a_c]) = bR[l];
        }
    };

    const int grp = lane >> 3;          // 0..3
    const int wi  = lane & 7;           // 0..7

    auto compute = [&](int s) {
        const uint32_t sa  = smem_u32(&Asm[s][0]);
        const uint32_t sbm = smem_u32(&Bsm[s][0]);
#pragma unroll
        for (int ks = 0; ks < 2; ks++) {
            uint32_t af[4][4], bf[4][2];
            // A fragments: 4 m16k16 tiles
#pragma unroll
            for (int mt = 0; mt < 4; mt++) {
                int r  = wm * 64 + mt * 16 + (grp & 1) * 8 + wi;
                int kh = ks * 16 + (grp >> 1) * 8;
                LDSM_X4(af[mt][0], af[mt][1], af[mt][2], af[mt][3],
                        sa + (uint32_t)(r * (SSTR * 2) + kh * 2));
            }
            // B fragments: 2 ldmatrix.x4, each covers two n8 tiles
#pragma unroll
            for (int hb = 0; hb < 2; hb++) {
                int r  = wn * 32 + hb * 16 + (grp >> 1) * 8 + wi;
                int kh = ks * 16 + (grp & 1) * 8;
                LDSM_X4(bf[2 * hb][0], bf[2 * hb][1],
                        bf[2 * hb + 1][0], bf[2 * hb + 1][1],
                        sbm + (uint32_t)(r * (SSTR * 2) + kh * 2));
            }
#pragma unroll
            for (int mt = 0; mt < 4; mt++)
#pragma unroll
                for (int nt = 0; nt < 4; nt++)
                    MMA_16816(acc[mt][nt], af[mt], bf[nt]);
        }
    };

    // ---- pipelined mainloop ----
    ldg_tile(0);
    sts_tile(0);
    __syncthreads();

    const int niter = K / 32;
    for (int it = 0; it < niter; it++) {
        int cur = it & 1;
        if (it + 1 < niter) ldg_tile((it + 1) * 32);
        compute(cur);
        if (it + 1 < niter) {
            sts_tile(cur ^ 1);
            __syncthreads();
        }
    }

    // ---- epilogue (c-frag: row g(+8), cols 2*tg) ----
    const int g  = lane >> 2;
    const int tg = lane & 3;
    float aval = 0.0f;
    if (MODE == 2) aval = *aptr;
    const int rbase = row0 + wm * 64;
    const int cbase = col0 + wn * 32;
#pragma unroll
    for (int mt = 0; mt < 4; mt++)
#pragma unroll
        for (int nt = 0; nt < 4; nt++)
#pragma unroll
            for (int hh = 0; hh < 2; hh++) {
                int r = rbase + mt * 16 + g + 8 * hh;
                int c = cbase + nt * 8 + 2 * tg;
                float o0 = acc[mt][nt][2 * hh + 0];
                float o1 = acc[mt][nt][2 * hh + 1];
                size_t base = (size_t)r * N + c;
                if (MODE == 0) {
                    o0 += bias[c]; o1 += bias[c + 1];
                } else if (MODE == 1) {
                    o0 *= scale; o1 *= scale;
                } else {
                    o0 = aval * hres[base]     + o0;
                    o1 = aval * hres[base + 1] + o1;
                }
                *reinterpret_cast<float2*>(&C[base]) = make_float2(o0, o1);
            }
}

// ---------------------------------------------------------------------------
// transpose: out[c][r] = in[r][c]
// ---------------------------------------------------------------------------
__global__ __launch_bounds__(256) void transpose_kernel(
    const float* __restrict__ in, float* __restrict__ out, int R, int Cc)
{
    __shared__ float t[32][33];
    int r0 = blockIdx.y * 32, c0 = blockIdx.x * 32;
#pragma unroll
    for (int i = threadIdx.y; i < 32; i += 8)
        t[i][threadIdx.x] = in[(size_t)(r0 + i) * Cc + c0 + threadIdx.x];
    __syncthreads();
#pragma unroll
    for (int i = threadIdx.y; i < 32; i += 8)
        out[(size_t)(c0 + i) * R + r0 + threadIdx.x] = t[threadIdx.x][i];
}

// vT[n][j] = v[j][n] * (1-a)
__global__ __launch_bounds__(256) void vprime_t_kernel(const float* __restrict__ aptr)
{
    __shared__ float t[32][33];
    int j0 = blockIdx.y * 32, n0 = blockIdx.x * 32;
    float av = 1.0f - *aptr;
#pragma unroll
    for (int i = threadIdx.y; i < 32; i += 8)
        t[i][threadIdx.x] = g_v[(size_t)(j0 + i) * HID + n0 + threadIdx.x] * av;
    __syncthreads();
#pragma unroll
    for (int i = threadIdx.y; i < 32; i += 8)
        g_vT[(size_t)(n0 + i) * N_TOK + j0 + threadIdx.x] = t[threadIdx.x][i];
}

// ---------------------------------------------------------------------------
// column softmax stats (softmax over dim 0): LZ[j] = m[j] + ln Z[j]
// ---------------------------------------------------------------------------
__global__ __launch_bounds__(256) void colstats_partial(const float* __restrict__ S)
{
    int j  = blockIdx.x * 256 + threadIdx.x;
    int i0 = blockIdx.y * ROWS_PER_CHUNK;
    float mx = -INFINITY, s = 0.0f;
    for (int i = i0; i < i0 + ROWS_PER_CHUNK; i++) {
        float x  = S[(size_t)i * N_TOK + j];
        float mn = fmaxf(mx, x);
        s = s * __expf(mx - mn) + __expf(x - mn);
        mx = mn;
    }
    g_pm[blockIdx.y * N_TOK + j] = mx;
    g_pZ[blockIdx.y * N_TOK + j] = s;
}

__global__ __launch_bounds__(256) void colstats_combine()
{
    int j = blockIdx.x * 256 + threadIdx.x;
    float mx = -INFINITY, s = 0.0f;
#pragma unroll
    for (int c = 0; c < NCHUNK; c++) {
        float mc = g_pm[c * N_TOK + j];
        float zc = g_pZ[c * N_TOK + j];
        float mn = fmaxf(mx, mc);
        s  = s * __expf(mx - mn) + zc * __expf(mc - mn);
        mx = mn;
    }
    g_LZ[j] = mx + logf(s);
}

// ---------------------------------------------------------------------------
extern "C" void kernel_launch(void* const* d_in, const int* in_sizes, int n_in,
                              void* d_out, int out_size)
{
    const float* x  = (const float*)d_in[0];
    const float* W1 = (const float*)d_in[1];
    const float* b1 = (const float*)d_in[2];
    const float* Wq = (const float*)d_in[3];
    const float* bq = (const float*)d_in[4];
    const float* Wk = (const float*)d_in[5];
    const float* bk = (const float*)d_in[6];
    const float* Wv = (const float*)d_in[7];
    const float* bv = (const float*)d_in[8];
    const float* a  = (const float*)d_in[9];
    const float* W2 = (const float*)d_in[10];
    const float* b2 = (const float*)d_in[11];
    float* out = (float*)d_out;

    float *h, *q, *k, *v, *h2, *S, *LZ;
    float *W1t, *Wqt, *Wkt, *Wvt, *W2t, *vT;
    cudaGetSymbolAddress((void**)&h,   g_h);
    cudaGetSymbolAddress((void**)&q,   g_q);
    cudaGetSymbolAddress((void**)&k,   g_k);
    cudaGetSymbolAddress((void**)&v,   g_v);
    cudaGetSymbolAddress((void**)&h2,  g_h2);
    cudaGetSymbolAddress((void**)&S,   g_S);
    cudaGetSymbolAddress((void**)&LZ,  g_LZ);
    cudaGetSymbolAddress((void**)&W1t, g_W1t);
    cudaGetSymbolAddress((void**)&Wqt, g_Wqt);
    cudaGetSymbolAddress((void**)&Wkt, g_Wkt);
    cudaGetSymbolAddress((void**)&Wvt, g_Wvt);
    cudaGetSymbolAddress((void**)&W2t, g_W2t);
    cudaGetSymbolAddress((void**)&vT,  g_vT);

    const float scale = 0.0625f; // 1/sqrt(256)
    dim3 tb(32, 8);

    // 0) transpose weights to [N,K] row-major (NT form)
    transpose_kernel<<<dim3(HID / 32,  D_IN / 32), tb>>>(W1, W1t, D_IN, HID);
    transpose_kernel<<<dim3(HID / 32,  HID / 32),  tb>>>(Wq, Wqt, HID, HID);
    transpose_kernel<<<dim3(HID / 32,  HID / 32),  tb>>>(Wk, Wkt, HID, HID);
    transpose_kernel<<<dim3(HID / 32,  HID / 32),  tb>>>(Wv, Wvt, HID, HID);
    transpose_kernel<<<dim3(C_OUT / 32, HID / 32), tb>>>(W2, W2t, HID, C_OUT);

    // 1) h = x @ W1 + b1
    hmma_gemm<0, false><<<dim3(HID / 128, N_TOK / 128), 256>>>(
        x, W1t, h, N_TOK, HID, D_IN, b1, 0.f, nullptr, nullptr, nullptr);
    // 2) q,k,v
    hmma_gemm<0, false><<<dim3(HID / 128, N_TOK / 128), 256>>>(
        h, Wqt, q, N_TOK, HID, HID, bq, 0.f, nullptr, nullptr, nullptr);
    hmma_gemm<0, false><<<dim3(HID / 128, N_TOK / 128), 256>>>(
        h, Wkt, k, N_TOK, HID, HID, bk, 0.f, nullptr, nullptr, nullptr);
    hmma_gemm<0, false><<<dim3(HID / 128, N_TOK / 128), 256>>>(
        h, Wvt, v, N_TOK, HID, HID, bv, 0.f, nullptr, nullptr, nullptr);
    // 3) S = (q @ k^T) * scale  (k is [token][hid] = NT form already)
    hmma_gemm<1, false><<<dim3(N_TOK / 128, N_TOK / 128), 256>>>(
        q, k, S, N_TOK, N_TOK, HID, nullptr, scale, nullptr, nullptr, nullptr);
    // 4) column softmax stats -> LZ = m + lnZ
    colstats_partial<<<dim3(N_TOK / 256, NCHUNK), 256>>>(S);
    colstats_combine<<<N_TOK / 256, 256>>>();
    // 5) vT = (v * (1-a))^T
    vprime_t_kernel<<<dim3(HID / 32, N_TOK / 32), tb>>>(a);
    // 6) h2 = a*h + exp(S - LZ[col]) @ vT^T   (exp fused into A prefetch)
    hmma_gemm<2, true><<<dim3(HID / 128, N_TOK / 128), 256>>>(
        S, vT, h2, N_TOK, HID, N_TOK, nullptr, 0.f, h, a, LZ);
    // 7) out = h2 @ W2 + b2
    hmma_gemm<0, false><<<dim3(C_OUT / 128, N_TOK / 128), 256>>>(
        h2, W2t, out, N_TOK, C_OUT, HID, b2, 0.f, nullptr, nullptr, nullptr);

    (void)in_sizes; (void)n_in; (void)out_size;
}

// round 9
// speedup vs baseline: 4.8472x; 1.3725x over previous
#include <cuda_runtime.h>
#include <cuda_fp16.h>
#include <stdint.h>
#include <math.h>

#define N_TOK 8192
#define D_IN  512
#define HID   256
#define C_OUT 256
#define NCHUNK 64            // one stats chunk per 128-row S-GEMM CTA row-block

// ---- scratch (static __device__, allocation-free) ----
__device__ float g_h  [N_TOK * HID];
__device__ float g_qkv[N_TOK * 3 * HID];          // [8192][768] q|k|v
__device__ float g_h2 [N_TOK * HID];
__device__ float g_S  [(size_t)N_TOK * N_TOK];
__device__ float g_pm [NCHUNK * N_TOK];
__device__ float g_pZ [NCHUNK * N_TOK];
__device__ float g_LZ [N_TOK];                    // m + ln Z per column
__device__ float g_W1t[HID * D_IN];
__device__ float g_Wqkvt[3 * HID * HID];          // [768][256]
__device__ float g_bqkv[3 * HID];
__device__ float g_W2t[C_OUT * HID];
__device__ float g_vT [HID * N_TOK];              // (v*(1-a))^T : [256][8192]

__device__ __forceinline__ uint32_t smem_u32(const void* p) {
    uint32_t a;
    asm("{ .reg .u64 t; cvta.to.shared.u64 t, %1; cvt.u32.u64 %0, t; }"
        : "=r"(a) : "l"(p));
    return a;
}

__device__ __forceinline__ uint2 pack_f4(float4 v) {
    __half2 h0 = __floats2half2_rn(v.x, v.y);
    __half2 h1 = __floats2half2_rn(v.z, v.w);
    uint2 u;
    u.x = *reinterpret_cast<uint32_t*>(&h0);
    u.y = *reinterpret_cast<uint32_t*>(&h1);
    return u;
}

#define LDSM_X4(r0, r1, r2, r3, addr) \
    asm volatile("ldmatrix.sync.aligned.m8n8.x4.shared.b16 {%0,%1,%2,%3}, [%4];" \
        : "=r"(r0), "=r"(r1), "=r"(r2), "=r"(r3) : "r"(addr))

#define MMA_16816(c, a, b) \
    asm volatile("mma.sync.aligned.m16n8k16.row.col.f32.f16.f16.f32 " \
        "{%0,%1,%2,%3}, {%4,%5,%6,%7}, {%8,%9}, {%0,%1,%2,%3};" \
        : "+f"((c)[0]), "+f"((c)[1]), "+f"((c)[2]), "+f"((c)[3]) \
        : "r"((a)[0]), "r"((a)[1]), "r"((a)[2]), "r"((a)[3]), \
          "r"((b)[0]), "r"((b)[1]))

#define SSTR 40   // smem row stride in halves; conflict-free LDSM phases

// ---------------------------------------------------------------------------
// fp16 tensor-core NT GEMM: C[M,N] = A[M,K'] @ Bt[N,K']^T, K' slice per grid.z
// MODE 0: C = acc + bias[col]
// MODE 1: C = acc * scale            (+ STATS: per-CTA column max/sumexp)
// MODE 3: atomicAdd(C, acc)          (split-K accumulation)
// EXP_A: A elements become exp(A - lzcol[k]) while prefetching.
// CTA 128x128, BK=32, 256 thr (8 warps 2x4), warp 64x32, double-buffered.
// ---------------------------------------------------------------------------
template <int MODE, bool EXP_A, bool STATS>
__global__ __launch_bounds__(256, 2) void hmma_gemm(
    const float* __restrict__ A, const float* __restrict__ Bt,
    float* __restrict__ C, int N, int K, int lda, int ldb,
    const float* __restrict__ bias, float scale,
    const float* __restrict__ lzcol,
    float* __restrict__ pm, float* __restrict__ pZ)
{
    __shared__ __align__(16) __half Asm[2][128 * SSTR];
    __shared__ __align__(16) __half Bsm[2][128 * SSTR];
    __shared__ float2 statS[STATS ? 128 : 1][2];

    const int tid  = threadIdx.x;
    const int lane = tid & 31;
    const int wid  = tid >> 5;
    const int wm   = wid >> 2;
    const int wn   = wid & 3;
    const int row0 = blockIdx.y * 128;
    const int col0 = blockIdx.x * 128;
    const int koff = blockIdx.z * K;

    const int a_r = tid >> 3;
    const int a_c = (tid & 7) * 4;

    float acc[4][4][4];
#pragma unroll
    for (int i = 0; i < 4; i++)
#pragma unroll
        for (int j = 0; j < 4; j++)
#pragma unroll
            for (int r = 0; r < 4; r++) acc[i][j][r] = 0.0f;

    uint2 aR[4], bR[4];

    auto ldg_tile = [&](int k0) {
#pragma unroll
        for (int l = 0; l < 4; l++) {
            int r = a_r + 32 * l;
            float4 v = *reinterpret_cast<const float4*>(
                &A[(size_t)(row0 + r) * lda + koff + k0 + a_c]);
            if (EXP_A) {
                float4 mv = *reinterpret_cast<const float4*>(&lzcol[koff + k0 + a_c]);
                v.x = __expf(v.x - mv.x); v.y = __expf(v.y - mv.y);
                v.z = __expf(v.z - mv.z); v.w = __expf(v.w - mv.w);
            }
            aR[l] = pack_f4(v);
            bR[l] = pack_f4(*reinterpret_cast<const float4*>(
                &Bt[(size_t)(col0 + r) * ldb + koff + k0 + a_c]));
        }
    };

    auto sts_tile = [&](int s) {
#pragma unroll
        for (int l = 0; l < 4; l++) {
            int r = a_r + 32 * l;
            *reinterpret_cast<uint2*>(&Asm[s][r * SSTR + a_c]) = aR[l];
            *reinterpret_cast<uint2*>(&Bsm[s][r * SSTR + a_c]) = bR[l];
        }
    };

    const int grp = lane >> 3;
    const int wi  = lane & 7;

    auto compute = [&](int s) {
        const uint32_t sa  = smem_u32(&Asm[s][0]);
        const uint32_t sbm = smem_u32(&Bsm[s][0]);
#pragma unroll
        for (int ks = 0; ks < 2; ks++) {
            uint32_t af[4][4], bf[4][2];
#pragma unroll
            for (int mt = 0; mt < 4; mt++) {
                int r  = wm * 64 + mt * 16 + (grp & 1) * 8 + wi;
                int kh = ks * 16 + (grp >> 1) * 8;
                LDSM_X4(af[mt][0], af[mt][1], af[mt][2], af[mt][3],
                        sa + (uint32_t)(r * (SSTR * 2) + kh * 2));
            }
#pragma unroll
            for (int hb = 0; hb < 2; hb++) {
                int r  = wn * 32 + hb * 16 + (grp >> 1) * 8 + wi;
                int kh = ks * 16 + (grp & 1) * 8;
                LDSM_X4(bf[2 * hb][0], bf[2 * hb][1],
                        bf[2 * hb + 1][0], bf[2 * hb + 1][1],
                        sbm + (uint32_t)(r * (SSTR * 2) + kh * 2));
            }
#pragma unroll
            for (int mt = 0; mt < 4; mt++)
#pragma unroll
                for (int nt = 0; nt < 4; nt++)
                    MMA_16816(acc[mt][nt], af[mt], bf[nt]);
        }
    };

    ldg_tile(0);
    sts_tile(0);
    __syncthreads();

    const int niter = K / 32;
    for (int it = 0; it < niter; it++) {
        int cur = it & 1;
        if (it + 1 < niter) ldg_tile((it + 1) * 32);
        compute(cur);
        if (it + 1 < niter) {
            sts_tile(cur ^ 1);
            __syncthreads();
        }
    }

    // ---- epilogue ----
    const int g  = lane >> 2;
    const int tg = lane & 3;
    const int rbase = row0 + wm * 64;
    const int cbase = col0 + wn * 32;
#pragma unroll
    for (int mt = 0; mt < 4; mt++)
#pragma unroll
        for (int nt = 0; nt < 4; nt++)
#pragma unroll
            for (int hh = 0; hh < 2; hh++) {
                int r = rbase + mt * 16 + g + 8 * hh;
                int c = cbase + nt * 8 + 2 * tg;
                float o0 = acc[mt][nt][2 * hh + 0];
                float o1 = acc[mt][nt][2 * hh + 1];
                size_t base = (size_t)r * N + c;
                if (MODE == 0) {
                    o0 += bias[c]; o1 += bias[c + 1];
                    *reinterpret_cast<float2*>(&C[base]) = make_float2(o0, o1);
                } else if (MODE == 1) {
                    o0 *= scale; o1 *= scale;
                    *reinterpret_cast<float2*>(&C[base]) = make_float2(o0, o1);
                } else {
                    atomicAdd(&C[base],     o0);
                    atomicAdd(&C[base + 1], o1);
                }
            }

    if (STATS) {
        // per-CTA column stats over its 128 rows (scaled scores)
#pragma unroll
        for (int nt = 0; nt < 4; nt++)
#pragma unroll
            for (int j = 0; j < 2; j++) {
                float m = -INFINITY;
#pragma unroll
                for (int mt = 0; mt < 4; mt++)
#pragma unroll
                    for (int hh = 0; hh < 2; hh++)
                        m = fmaxf(m, acc[mt][nt][2 * hh + j] * scale);
                float s = 0.0f;
#pragma unroll
                for (int mt = 0; mt < 4; mt++)
#pragma unroll
                    for (int hh = 0; hh < 2; hh++)
                        s += __expf(acc[mt][nt][2 * hh + j] * scale - m);
                // reduce over g (lanes g*4+tg): masks 4,8,16
#pragma unroll
                for (int msk = 4; msk <= 16; msk <<= 1) {
                    float om = __shfl_xor_sync(0xffffffffu, m, msk);
                    float os = __shfl_xor_sync(0xffffffffu, s, msk);
                    float nm = fmaxf(m, om);
                    s = s * __expf(m - nm) + os * __expf(om - nm);
                    m = nm;
                }
                if (g == 0) {
                    int c = wn * 32 + nt * 8 + 2 * tg + j;
                    statS[c][wm] = make_float2(m, s);
                }
            }
        __syncthreads();
        if (tid < 128) {
            float2 s0 = statS[tid][0];
            float2 s1 = statS[tid][1];
            float nm = fmaxf(s0.x, s1.x);
            float ss = s0.y * __expf(s0.x - nm) + s1.y * __expf(s1.x - nm);
            pm[(size_t)blockIdx.y * N_TOK + col0 + tid] = nm;
            pZ[(size_t)blockIdx.y * N_TOK + col0 + tid] = ss;
        }
    }
}

// ---------------------------------------------------------------------------
__global__ __launch_bounds__(256) void transpose_kernel(
    const float* __restrict__ in, float* __restrict__ out, int R, int Cc)
{
    __shared__ float t[32][33];
    int r0 = blockIdx.y * 32, c0 = blockIdx.x * 32;
#pragma unroll
    for (int i = threadIdx.y; i < 32; i += 8)
        t[i][threadIdx.x] = in[(size_t)(r0 + i) * Cc + c0 + threadIdx.x];
    __syncthreads();
#pragma unroll
    for (int i = threadIdx.y; i < 32; i += 8)
        out[(size_t)(c0 + i) * R + r0 + threadIdx.x] = t[threadIdx.x][i];
}

__global__ void concat_bias_kernel(const float* __restrict__ bq,
                                   const float* __restrict__ bk,
                                   const float* __restrict__ bv)
{
    int i = blockIdx.x * 256 + threadIdx.x;   // 0..767
    float val = (i < 256) ? bq[i] : (i < 512) ? bk[i - 256] : bv[i - 512];
    g_bqkv[i] = val;
}

// vT[n][j] = qkv[j][512+n] * (1-a)
__global__ __launch_bounds__(256) void vprime_t_kernel(const float* __restrict__ aptr)
{
    __shared__ float t[32][33];
    int j0 = blockIdx.y * 32, n0 = blockIdx.x * 32;
    float av = 1.0f - *aptr;
#pragma unroll
    for (int i = threadIdx.y; i < 32; i += 8)
        t[i][threadIdx.x] =
            g_qkv[(size_t)(j0 + i) * 768 + 512 + n0 + threadIdx.x] * av;
    __syncthreads();
#pragma unroll
    for (int i = threadIdx.y; i < 32; i += 8)
        g_vT[(size_t)(n0 + i) * N_TOK + j0 + threadIdx.x] = t[threadIdx.x][i];
}

// h2 = a * h   (PV split-K partials atomically accumulate on top)
__global__ __launch_bounds__(256) void init_h2_kernel(const float* __restrict__ aptr)
{
    float av = *aptr;
    size_t base = ((size_t)blockIdx.x * 256 + threadIdx.x) * 4;
    float4 x = *reinterpret_cast<const float4*>(&g_h[base]);
    x.x *= av; x.y *= av; x.z *= av; x.w *= av;
    *reinterpret_cast<float4*>(&g_h2[base]) = x;
}

// combine 64 per-rowblock partials -> LZ[j] = m + ln Z
__global__ __launch_bounds__(256) void colstats_combine()
{
    int j = blockIdx.x * 256 + threadIdx.x;
    float mx = -INFINITY, s = 0.0f;
#pragma unroll 8
    for (int c = 0; c < NCHUNK; c++) {
        float mc = g_pm[(size_t)c * N_TOK + j];
        float zc = g_pZ[(size_t)c * N_TOK + j];
        float mn = fmaxf(mx, mc);
        s  = s * __expf(mx - mn) + zc * __expf(mc - mn);
        mx = mn;
    }
    g_LZ[j] = mx + logf(s);
}

// ---------------------------------------------------------------------------
extern "C" void kernel_launch(void* const* d_in, const int* in_sizes, int n_in,
                              void* d_out, int out_size)
{
    const float* x  = (const float*)d_in[0];
    const float* W1 = (const float*)d_in[1];
    const float* b1 = (const float*)d_in[2];
    const float* Wq = (const float*)d_in[3];
    const float* bq = (const float*)d_in[4];
    const float* Wk = (const float*)d_in[5];
    const float* bk = (const float*)d_in[6];
    const float* Wv = (const float*)d_in[7];
    const float* bv = (const float*)d_in[8];
    const float* a  = (const float*)d_in[9];
    const float* W2 = (const float*)d_in[10];
    const float* b2 = (const float*)d_in[11];
    float* out = (float*)d_out;

    float *h, *qkv, *h2, *S, *LZ, *pm, *pZ;
    float *W1t, *Wqkvt, *bqkv, *W2t, *vT;
    cudaGetSymbolAddress((void**)&h,     g_h);
    cudaGetSymbolAddress((void**)&qkv,   g_qkv);
    cudaGetSymbolAddress((void**)&h2,    g_h2);
    cudaGetSymbolAddress((void**)&S,     g_S);
    cudaGetSymbolAddress((void**)&LZ,    g_LZ);
    cudaGetSymbolAddress((void**)&pm,    g_pm);
    cudaGetSymbolAddress((void**)&pZ,    g_pZ);
    cudaGetSymbolAddress((void**)&W1t,   g_W1t);
    cudaGetSymbolAddress((void**)&Wqkvt, g_Wqkvt);
    cudaGetSymbolAddress((void**)&bqkv,  g_bqkv);
    cudaGetSymbolAddress((void**)&W2t,   g_W2t);
    cudaGetSymbolAddress((void**)&vT,    g_vT);

    const float scale = 0.0625f; // 1/sqrt(256)
    dim3 tb(32, 8);

    // 0) transpose weights (NT form); concat qkv weights/biases
    transpose_kernel<<<dim3(HID / 32,  D_IN / 32), tb>>>(W1, W1t, D_IN, HID);
    transpose_kernel<<<dim3(HID / 32,  HID / 32),  tb>>>(Wq, Wqkvt,             HID, HID);
    transpose_kernel<<<dim3(HID / 32,  HID / 32),  tb>>>(Wk, Wqkvt + HID * HID, HID, HID);
    transpose_kernel<<<dim3(HID / 32,  HID / 32),  tb>>>(Wv, Wqkvt + 2 * HID * HID, HID, HID);
    transpose_kernel<<<dim3(C_OUT / 32, HID / 32), tb>>>(W2, W2t, HID, C_OUT);
    concat_bias_kernel<<<3, 256>>>(bq, bk, bv);

    // 1) h = x @ W1 + b1
    hmma_gemm<0, false, false><<<dim3(HID / 128, N_TOK / 128, 1), 256>>>(
        x, W1t, h, HID, D_IN, D_IN, D_IN, b1, 0.f, nullptr, nullptr, nullptr);
    // 2) qkv = h @ Wqkv + bqkv   (one fused launch, N=768)
    hmma_gemm<0, false, false><<<dim3(768 / 128, N_TOK / 128, 1), 256>>>(
        h, Wqkvt, qkv, 768, HID, HID, HID, bqkv, 0.f, nullptr, nullptr, nullptr);
    // 3) S = (q @ k^T) * scale, with fused per-rowblock column stats
    hmma_gemm<1, false, true><<<dim3(N_TOK / 128, N_TOK / 128, 1), 256>>>(
        qkv, qkv + HID, S, N_TOK, HID, 768, 768, nullptr, scale, nullptr, pm, pZ);
    // 4) combine stats -> LZ
    colstats_combine<<<N_TOK / 256, 256>>>();
    // 5) vT = (v * (1-a))^T ; h2 = a*h
    vprime_t_kernel<<<dim3(HID / 32, N_TOK / 32), tb>>>(a);
    init_h2_kernel<<<N_TOK * HID / 4 / 256, 256>>>(a);
    // 6) h2 += exp(S - LZ[col]) @ vT^T   (split-K=2, atomic accumulate)
    hmma_gemm<3, true, false><<<dim3(HID / 128, N_TOK / 128, 2), 256>>>(
        S, vT, h2, HID, N_TOK / 2, N_TOK, N_TOK, nullptr, 0.f, LZ, nullptr, nullptr);
    // 7) out = h2 @ W2 + b2
    hmma_gemm<0, false, false><<<dim3(C_OUT / 128, N_TOK / 128, 1), 256>>>(
        h2, W2t, out, C_OUT, HID, HID, HID, b2, 0.f, nullptr, nullptr, nullptr);

    (void)in_sizes; (void)n_in; (void)out_size;
}

// round 10
// speedup vs baseline: 5.4836x; 1.1313x over previous
#include <cuda_runtime.h>
#include <cuda_fp16.h>
#include <stdint.h>
#include <math.h>

#define N_TOK 8192
#define D_IN  512
#define HID   256
#define C_OUT 256
#define NCHUNK 64

// ---- scratch (static __device__, allocation-free) ----
__device__ __half g_h  [N_TOK * HID];
__device__ __half g_qkv[N_TOK * 3 * HID];          // [8192][768] q|k|v
__device__ float  g_h2 [N_TOK * HID];              // f32 (atomic accum)
__device__ __half g_S  [(size_t)N_TOK * N_TOK];    // scaled scores, fp16
__device__ float  g_pm [NCHUNK * N_TOK];
__device__ float  g_pZ [NCHUNK * N_TOK];
__device__ float  g_LZ [N_TOK];                    // m + ln Z per column
__device__ __half g_W1t[HID * D_IN];
__device__ __half g_Wqkvt[3 * HID * HID];          // [768][256]
__device__ float  g_bqkv[3 * HID];
__device__ __half g_W2t[C_OUT * HID];
__device__ __half g_vT [HID * N_TOK];              // (v*(1-a))^T : [256][8192]

__device__ __forceinline__ uint32_t smem_u32(const void* p) {
    uint32_t a;
    asm("{ .reg .u64 t; cvta.to.shared.u64 t, %1; cvt.u32.u64 %0, t; }"
        : "=r"(a) : "l"(p));
    return a;
}

__device__ __forceinline__ uint2 pack_f4(float4 v) {
    __half2 h0 = __floats2half2_rn(v.x, v.y);
    __half2 h1 = __floats2half2_rn(v.z, v.w);
    uint2 u;
    u.x = *reinterpret_cast<uint32_t*>(&h0);
    u.y = *reinterpret_cast<uint32_t*>(&h1);
    return u;
}

#define LDSM_X4(r0, r1, r2, r3, addr) \
    asm volatile("ldmatrix.sync.aligned.m8n8.x4.shared.b16 {%0,%1,%2,%3}, [%4];" \
        : "=r"(r0), "=r"(r1), "=r"(r2), "=r"(r3) : "r"(addr))

#define MMA_16816(c, a, b) \
    asm volatile("mma.sync.aligned.m16n8k16.row.col.f32.f16.f16.f32 " \
        "{%0,%1,%2,%3}, {%4,%5,%6,%7}, {%8,%9}, {%0,%1,%2,%3};" \
        : "+f"((c)[0]), "+f"((c)[1]), "+f"((c)[2]), "+f"((c)[3]) \
        : "r"((a)[0]), "r"((a)[1]), "r"((a)[2]), "r"((a)[3]), \
          "r"((b)[0]), "r"((b)[1]))

#define SSTR 40   // smem row stride in halves; conflict-free LDSM phases

// ---------------------------------------------------------------------------
// fp16 tensor-core NT GEMM: C[M,N] = A[M,K'] @ Bt[N,K']^T, K' slice per grid.z
// MODE 0: C = acc + bias[col]
// MODE 1: C = acc * scale            (+ STATS: per-CTA column max/sumexp)
// MODE 3: atomicAdd(C, acc)          (split-K accumulation, C f32)
// AH/BH: A/B gmem dtype is fp16 (else f32).  CH: C stored fp16.
// EXP_A (requires AH): A becomes exp(A - lzcol[k]) during prefetch.
// CTA 128x128, BK=32, 256 thr (8 warps 2x4), warp 64x32, double-buffered.
// ---------------------------------------------------------------------------
template <int MODE, bool EXP_A, bool STATS, bool AH, bool BH, bool CH>
__global__ __launch_bounds__(256, 2) void hmma_gemm(
    const void* __restrict__ Av, const void* __restrict__ Bv,
    void* __restrict__ Cv, int N, int K, int lda, int ldb,
    const float* __restrict__ bias, float scale,
    const float* __restrict__ lzcol,
    float* __restrict__ pm, float* __restrict__ pZ)
{
    const float*  Af = (const float*)Av;
    const __half* Ah = (const __half*)Av;
    const float*  Bf = (const float*)Bv;
    const __half* Bh = (const __half*)Bv;
    float*  Cf = (float*)Cv;
    __half* Ch = (__half*)Cv;

    __shared__ __align__(16) __half Asm[2][128 * SSTR];
    __shared__ __align__(16) __half Bsm[2][128 * SSTR];
    __shared__ float2 statS[STATS ? 128 : 1][2];

    const int tid  = threadIdx.x;
    const int lane = tid & 31;
    const int wid  = tid >> 5;
    const int wm   = wid >> 2;
    const int wn   = wid & 3;
    const int row0 = blockIdx.y * 128;
    const int col0 = blockIdx.x * 128;
    const int koff = blockIdx.z * K;

    // f32 staging map
    const int a_r = tid >> 3;          // 0..31 (+32*l)
    const int a_c = (tid & 7) * 4;
    // f16 staging map
    const int h_r = tid >> 2;          // 0..63 (+64*l)
    const int h_c = (tid & 3) * 8;

    float acc[4][4][4];
#pragma unroll
    for (int i = 0; i < 4; i++)
#pragma unroll
        for (int j = 0; j < 4; j++)
#pragma unroll
            for (int r = 0; r < 4; r++) acc[i][j][r] = 0.0f;

    uint2 aF[4], bF[4];
    uint4 aH[2], bH[2];

    auto ldg_tile = [&](int k0) {
        if (AH) {
#pragma unroll
            for (int l = 0; l < 2; l++) {
                int r = h_r + 64 * l;
                uint4 v = *reinterpret_cast<const uint4*>(
                    &Ah[(size_t)(row0 + r) * lda + koff + k0 + h_c]);
                if (EXP_A) {
                    float4 l0 = *reinterpret_cast<const float4*>(&lzcol[koff + k0 + h_c]);
                    float4 l1 = *reinterpret_cast<const float4*>(&lzcol[koff + k0 + h_c + 4]);
                    __half2* p = reinterpret_cast<__half2*>(&v);
                    float2 f;
                    f = __half22float2(p[0]);
                    p[0] = __floats2half2_rn(__expf(f.x - l0.x), __expf(f.y - l0.y));
                    f = __half22float2(p[1]);
                    p[1] = __floats2half2_rn(__expf(f.x - l0.z), __expf(f.y - l0.w));
                    f = __half22float2(p[2]);
                    p[2] = __floats2half2_rn(__expf(f.x - l1.x), __expf(f.y - l1.y));
                    f = __half22float2(p[3]);
                    p[3] = __floats2half2_rn(__expf(f.x - l1.z), __expf(f.y - l1.w));
                }
                aH[l] = v;
            }
        } else {
#pragma unroll
            for (int l = 0; l < 4; l++) {
                int r = a_r + 32 * l;
                aF[l] = pack_f4(*reinterpret_cast<const float4*>(
                    &Af[(size_t)(row0 + r) * lda + koff + k0 + a_c]));
            }
        }
        if (BH) {
#pragma unroll
            for (int l = 0; l < 2; l++) {
                int r = h_r + 64 * l;
                bH[l] = *reinterpret_cast<const uint4*>(
                    &Bh[(size_t)(col0 + r) * ldb + koff + k0 + h_c]);
            }
        } else {
#pragma unroll
            for (int l = 0; l < 4; l++) {
                int r = a_r + 32 * l;
                bF[l] = pack_f4(*reinterpret_cast<const float4*>(
                    &Bf[(size_t)(col0 + r) * ldb + koff + k0 + a_c]));
            }
        }
    };

    auto sts_tile = [&](int s) {
        if (AH) {
#pragma unroll
            for (int l = 0; l < 2; l++) {
                int r = h_r + 64 * l;
                *reinterpret_cast<uint4*>(&Asm[s][r * SSTR + h_c]) = aH[l];
            }
        } else {
#pragma unroll
            for (int l = 0; l < 4; l++) {
                int r = a_r + 32 * l;
                *reinterpret_cast<uint2*>(&Asm[s][r * SSTR + a_c]) = aF[l];
            }
        }
        if (BH) {
#pragma unroll
            for (int l = 0; l < 2; l++) {
                int r = h_r + 64 * l;
                *reinterpret_cast<uint4*>(&Bsm[s][r * SSTR + h_c]) = bH[l];
            }
        } else {
#pragma unroll
            for (int l = 0; l < 4; l++) {
                int r = a_r + 32 * l;
                *reinterpret_cast<uint2*>(&Bsm[s][r * SSTR + a_c]) = bF[l];
            }
        }
    };

    const int grp = lane >> 3;
    const int wi  = lane & 7;

    auto compute = [&](int s) {
        const uint32_t sa  = smem_u32(&Asm[s][0]);
        const uint32_t sbm = smem_u32(&Bsm[s][0]);
#pragma unroll
        for (int ks = 0; ks < 2; ks++) {
            uint32_t af[4][4], bf[4][2];
#pragma unroll
            for (int mt = 0; mt < 4; mt++) {
                int r  = wm * 64 + mt * 16 + (grp & 1) * 8 + wi;
                int kh = ks * 16 + (grp >> 1) * 8;
                LDSM_X4(af[mt][0], af[mt][1], af[mt][2], af[mt][3],
                        sa + (uint32_t)(r * (SSTR * 2) + kh * 2));
            }
#pragma unroll
            for (int hb = 0; hb < 2; hb++) {
                int r  = wn * 32 + hb * 16 + (grp >> 1) * 8 + wi;
                int kh = ks * 16 + (grp & 1) * 8;
                LDSM_X4(bf[2 * hb][0], bf[2 * hb][1],
                        bf[2 * hb + 1][0], bf[2 * hb + 1][1],
                        sbm + (uint32_t)(r * (SSTR * 2) + kh * 2));
            }
#pragma unroll
            for (int mt = 0; mt < 4; mt++)
#pragma unroll
                for (int nt = 0; nt < 4; nt++)
                    MMA_16816(acc[mt][nt], af[mt], bf[nt]);
        }
    };

    ldg_tile(0);
    sts_tile(0);
    __syncthreads();

    const int niter = K / 32;
    for (int it = 0; it < niter; it++) {
        int cur = it & 1;
        if (it + 1 < niter) ldg_tile((it + 1) * 32);
        compute(cur);
        if (it + 1 < niter) {
            sts_tile(cur ^ 1);
            __syncthreads();
        }
    }

    // ---- epilogue ----
    const int g  = lane >> 2;
    const int tg = lane & 3;
    const int rbase = row0 + wm * 64;
    const int cbase = col0 + wn * 32;
#pragma unroll
    for (int mt = 0; mt < 4; mt++)
#pragma unroll
        for (int nt = 0; nt < 4; nt++)
#pragma unroll
            for (int hh = 0; hh < 2; hh++) {
                int r = rbase + mt * 16 + g + 8 * hh;
                int c = cbase + nt * 8 + 2 * tg;
                float o0 = acc[mt][nt][2 * hh + 0];
                float o1 = acc[mt][nt][2 * hh + 1];
                size_t base = (size_t)r * N + c;
                if (MODE == 0 || MODE == 1) {
                    if (MODE == 0) { o0 += bias[c]; o1 += bias[c + 1]; }
                    else           { o0 *= scale;  o1 *= scale; }
                    if (CH) {
                        *reinterpret_cast<__half2*>(&Ch[base]) =
                            __floats2half2_rn(o0, o1);
                    } else {
                        *reinterpret_cast<float2*>(&Cf[base]) = make_float2(o0, o1);
                    }
                } else {
                    atomicAdd(&Cf[base],     o0);
                    atomicAdd(&Cf[base + 1], o1);
                }
            }

    if (STATS) {
#pragma unroll
        for (int nt = 0; nt < 4; nt++)
#pragma unroll
            for (int j = 0; j < 2; j++) {
                float m = -INFINITY;
#pragma unroll
                for (int mt = 0; mt < 4; mt++)
#pragma unroll
                    for (int hh = 0; hh < 2; hh++)
                        m = fmaxf(m, acc[mt][nt][2 * hh + j] * scale);
                float s = 0.0f;
#pragma unroll
                for (int mt = 0; mt < 4; mt++)
#pragma unroll
                    for (int hh = 0; hh < 2; hh++)
                        s += __expf(acc[mt][nt][2 * hh + j] * scale - m);
#pragma unroll
                for (int msk = 4; msk <= 16; msk <<= 1) {
                    float om = __shfl_xor_sync(0xffffffffu, m, msk);
                    float os = __shfl_xor_sync(0xffffffffu, s, msk);
                    float nm = fmaxf(m, om);
                    s = s * __expf(m - nm) + os * __expf(om - nm);
                    m = nm;
                }
                if (g == 0) {
                    int c = wn * 32 + nt * 8 + 2 * tg + j;
                    statS[c][wm] = make_float2(m, s);
                }
            }
        __syncthreads();
        if (tid < 128) {
            float2 s0 = statS[tid][0];
            float2 s1 = statS[tid][1];
            float nm = fmaxf(s0.x, s1.x);
            float ss = s0.y * __expf(s0.x - nm) + s1.y * __expf(s1.x - nm);
            pm[(size_t)blockIdx.y * N_TOK + col0 + tid] = nm;
            pZ[(size_t)blockIdx.y * N_TOK + col0 + tid] = ss;
        }
    }
}

// ---------------------------------------------------------------------------
// transpose f32 -> fp16: out[c][r] = (half) in[r][c]
// ---------------------------------------------------------------------------
__global__ __launch_bounds__(256) void transpose_h_kernel(
    const float* __restrict__ in, __half* __restrict__ out, int R, int Cc)
{
    __shared__ float t[32][33];
    int r0 = blockIdx.y * 32, c0 = blockIdx.x * 32;
#pragma unroll
    for (int i = threadIdx.y; i < 32; i += 8)
        t[i][threadIdx.x] = in[(size_t)(r0 + i) * Cc + c0 + threadIdx.x];
    __syncthreads();
#pragma unroll
    for (int i = threadIdx.y; i < 32; i += 8)
        out[(size_t)(c0 + i) * R + r0 + threadIdx.x] = __float2half(t[threadIdx.x][i]);
}

__global__ void concat_bias_kernel(const float* __restrict__ bq,
                                   const float* __restrict__ bk,
                                   const float* __restrict__ bv)
{
    int i = blockIdx.x * 256 + threadIdx.x;
    float val = (i < 256) ? bq[i] : (i < 512) ? bk[i - 256] : bv[i - 512];
    g_bqkv[i] = val;
}

// vT[n][j] = qkv[j][512+n] * (1-a)   (fp16 in/out)
__global__ __launch_bounds__(256) void vprime_t_kernel(const float* __restrict__ aptr)
{
    __shared__ float t[32][33];
    int j0 = blockIdx.y * 32, n0 = blockIdx.x * 32;
    float av = 1.0f - *aptr;
#pragma unroll
    for (int i = threadIdx.y; i < 32; i += 8)
        t[i][threadIdx.x] =
            __half2float(g_qkv[(size_t)(j0 + i) * 768 + 512 + n0 + threadIdx.x]) * av;
    __syncthreads();
#pragma unroll
    for (int i = threadIdx.y; i < 32; i += 8)
        g_vT[(size_t)(n0 + i) * N_TOK + j0 + threadIdx.x] =
            __float2half(t[threadIdx.x][i]);
}

// h2 = a * h   (fp16 h -> f32 h2; PV split-K partials atomically accumulate)
__global__ __launch_bounds__(256) void init_h2_kernel(const float* __restrict__ aptr)
{
    float av = *aptr;
    size_t base = ((size_t)blockIdx.x * 256 + threadIdx.x) * 8;
    uint4 v = *reinterpret_cast<const uint4*>(&g_h[base]);
    const __half2* p = reinterpret_cast<const __half2*>(&v);
    float4 o0, o1;
    float2 f;
    f = __half22float2(p[0]); o0.x = av * f.x; o0.y = av * f.y;
    f = __half22float2(p[1]); o0.z = av * f.x; o0.w = av * f.y;
    f = __half22float2(p[2]); o1.x = av * f.x; o1.y = av * f.y;
    f = __half22float2(p[3]); o1.z = av * f.x; o1.w = av * f.y;
    *reinterpret_cast<float4*>(&g_h2[base])     = o0;
    *reinterpret_cast<float4*>(&g_h2[base + 4]) = o1;
}

// combine 64 per-rowblock partials -> LZ[j] = m + ln Z
__global__ __launch_bounds__(256) void colstats_combine()
{
    int j = blockIdx.x * 256 + threadIdx.x;
    float mx = -INFINITY, s = 0.0f;
#pragma unroll 8
    for (int c = 0; c < NCHUNK; c++) {
        float mc = g_pm[(size_t)c * N_TOK + j];
        float zc = g_pZ[(size_t)c * N_TOK + j];
        float mn = fmaxf(mx, mc);
        s  = s * __expf(mx - mn) + zc * __expf(mc - mn);
        mx = mn;
    }
    g_LZ[j] = mx + logf(s);
}

// ---------------------------------------------------------------------------
extern "C" void kernel_launch(void* const* d_in, const int* in_sizes, int n_in,
                              void* d_out, int out_size)
{
    const float* x  = (const float*)d_in[0];
    const float* W1 = (const float*)d_in[1];
    const float* b1 = (const float*)d_in[2];
    const float* Wq = (const float*)d_in[3];
    const float* bq = (const float*)d_in[4];
    const float* Wk = (const float*)d_in[5];
    const float* bk = (const float*)d_in[6];
    const float* Wv = (const float*)d_in[7];
    const float* bv = (const float*)d_in[8];
    const float* a  = (const float*)d_in[9];
    const float* W2 = (const float*)d_in[10];
    const float* b2 = (const float*)d_in[11];
    float* out = (float*)d_out;

    __half *h, *qkv, *S, *vT, *W1t, *Wqkvt, *W2t;
    float *h2, *LZ, *pm, *pZ, *bqkv;
    cudaGetSymbolAddress((void**)&h,     g_h);
    cudaGetSymbolAddress((void**)&qkv,   g_qkv);
    cudaGetSymbolAddress((void**)&h2,    g_h2);
    cudaGetSymbolAddress((void**)&S,     g_S);
    cudaGetSymbolAddress((void**)&LZ,    g_LZ);
    cudaGetSymbolAddress((void**)&pm,    g_pm);
    cudaGetSymbolAddress((void**)&pZ,    g_pZ);
    cudaGetSymbolAddress((void**)&W1t,   g_W1t);
    cudaGetSymbolAddress((void**)&Wqkvt, g_Wqkvt);
    cudaGetSymbolAddress((void**)&bqkv,  g_bqkv);
    cudaGetSymbolAddress((void**)&W2t,   g_W2t);
    cudaGetSymbolAddress((void**)&vT,    g_vT);

    const float scale = 0.0625f; // 1/sqrt(256)
    dim3 tb(32, 8);

    // 0) transpose weights to fp16 NT form; concat qkv weights/biases
    transpose_h_kernel<<<dim3(HID / 32,  D_IN / 32), tb>>>(W1, W1t, D_IN, HID);
    transpose_h_kernel<<<dim3(HID / 32,  HID / 32),  tb>>>(Wq, Wqkvt,             HID, HID);
    transpose_h_kernel<<<dim3(HID / 32,  HID / 32),  tb>>>(Wk, Wqkvt + HID * HID, HID, HID);
    transpose_h_kernel<<<dim3(HID / 32,  HID / 32),  tb>>>(Wv, Wqkvt + 2 * HID * HID, HID, HID);
    transpose_h_kernel<<<dim3(C_OUT / 32, HID / 32), tb>>>(W2, W2t, HID, C_OUT);
    concat_bias_kernel<<<3, 256>>>(bq, bk, bv);

    // 1) h = x @ W1 + b1          (A f32, B f16, C f16)
    hmma_gemm<0, false, false, false, true, true>
        <<<dim3(HID / 128, N_TOK / 128, 1), 256>>>(
        x, W1t, h, HID, D_IN, D_IN, D_IN, b1, 0.f, nullptr, nullptr, nullptr);
    // 2) qkv = h @ Wqkv + bqkv    (all f16)
    hmma_gemm<0, false, false, true, true, true>
        <<<dim3(768 / 128, N_TOK / 128, 1), 256>>>(
        h, Wqkvt, qkv, 768, HID, HID, HID, bqkv, 0.f, nullptr, nullptr, nullptr);
    // 3) S = (q @ k^T) * scale, fused per-rowblock column stats (S f16)
    hmma_gemm<1, false, true, true, true, true>
        <<<dim3(N_TOK / 128, N_TOK / 128, 1), 256>>>(
        qkv, qkv + HID, S, N_TOK, HID, 768, 768, nullptr, scale, nullptr, pm, pZ);
    // 4) combine stats -> LZ
    colstats_combine<<<N_TOK / 256, 256>>>();
    // 5) vT = (v * (1-a))^T ; h2 = a*h
    vprime_t_kernel<<<dim3(HID / 32, N_TOK / 32), tb>>>(a);
    init_h2_kernel<<<N_TOK * HID / 8 / 256, 256>>>(a);
    // 6) h2 += exp(S - LZ[col]) @ vT^T   (split-K=2, atomic f32 accumulate)
    hmma_gemm<3, true, false, true, true, false>
        <<<dim3(HID / 128, N_TOK / 128, 2), 256>>>(
        S, vT, h2, HID, N_TOK / 2, N_TOK, N_TOK, nullptr, 0.f, LZ, nullptr, nullptr);
    // 7) out = h2 @ W2 + b2       (A f32, B f16, C f32)
    hmma_gemm<0, false, false, false, true, false>
        <<<dim3(C_OUT / 128, N_TOK / 128, 1), 256>>>(
        h2, W2t, out, C_OUT, HID, HID, HID, b2, 0.f, nullptr, nullptr, nullptr);

    (void)in_sizes; (void)n_in; (void)out_size;
}

// round 11
// speedup vs baseline: 5.5104x; 1.0049x over previous
#include <cuda_runtime.h>
#include <cuda_fp16.h>
#include <stdint.h>
#include <math.h>

#define N_TOK 8192
#define D_IN  512
#define HID   256
#define C_OUT 256
#define NCHUNK 64

// ---- scratch (static __device__, allocation-free) ----
__device__ __half g_h  [N_TOK * HID];
__device__ __half g_qkv[N_TOK * 3 * HID];          // [8192][768] q|k|v
__device__ float  g_h2 [N_TOK * HID];              // f32 (atomic accum)
__device__ __half g_S  [(size_t)N_TOK * N_TOK];    // scaled scores, fp16
__device__ float  g_pm [NCHUNK * N_TOK];
__device__ float  g_pZ [NCHUNK * N_TOK];
__device__ float  g_LZ [N_TOK];                    // m + ln Z per column
__device__ __half g_W1t[HID * D_IN];
__device__ __half g_Wqkvt[3 * HID * HID];          // [768][256]
__device__ float  g_bqkv[3 * HID];
__device__ __half g_W2t[C_OUT * HID];
__device__ __half g_vT [HID * N_TOK];              // (v*(1-a))^T : [256][8192]

__device__ __forceinline__ uint32_t smem_u32(const void* p) {
    uint32_t a;
    asm("{ .reg .u64 t; cvta.to.shared.u64 t, %1; cvt.u32.u64 %0, t; }"
        : "=r"(a) : "l"(p));
    return a;
}

__device__ __forceinline__ uint2 pack_f4(float4 v) {
    __half2 h0 = __floats2half2_rn(v.x, v.y);
    __half2 h1 = __floats2half2_rn(v.z, v.w);
    uint2 u;
    u.x = *reinterpret_cast<uint32_t*>(&h0);
    u.y = *reinterpret_cast<uint32_t*>(&h1);
    return u;
}

#define LDSM_X4(r0, r1, r2, r3, addr) \
    asm volatile("ldmatrix.sync.aligned.m8n8.x4.shared.b16 {%0,%1,%2,%3}, [%4];" \
        : "=r"(r0), "=r"(r1), "=r"(r2), "=r"(r3) : "r"(addr))

#define MMA_16816(c, a, b) \
    asm volatile("mma.sync.aligned.m16n8k16.row.col.f32.f16.f16.f32 " \
        "{%0,%1,%2,%3}, {%4,%5,%6,%7}, {%8,%9}, {%0,%1,%2,%3};" \
        : "+f"((c)[0]), "+f"((c)[1]), "+f"((c)[2]), "+f"((c)[3]) \
        : "r"((a)[0]), "r"((a)[1]), "r"((a)[2]), "r"((a)[3]), \
          "r"((b)[0]), "r"((b)[1]))

#define SSTR 40   // smem row stride in halves; conflict-free LDSM phases

// ---------------------------------------------------------------------------
// fp16 tensor-core NT GEMM: C[M,N] = A[M,K'] @ Bt[N,K']^T, K' slice per grid.z
// MODE 0: C = acc + bias[col]
// MODE 1: C = acc * scale            (+ STATS: per-CTA column max/sumexp)
// MODE 3: atomicAdd(C, acc)          (split-K accumulation, C f32)
// AH/BH: A/B gmem dtype fp16 (else f32).  CH: C stored fp16.
// EXP_A (requires AH): A becomes exp(A - lzcol[k]) during prefetch.
// CTA 128x128, BK=32, 128 threads (4 warps 2x2), warp tile 64x64,
// double-buffered register->smem pipeline.
// ---------------------------------------------------------------------------
template <int MODE, bool EXP_A, bool STATS, bool AH, bool BH, bool CH>
__global__ __launch_bounds__(128, 2) void hmma_gemm(
    const void* __restrict__ Av, const void* __restrict__ Bv,
    void* __restrict__ Cv, int N, int K, int lda, int ldb,
    const float* __restrict__ bias, float scale,
    const float* __restrict__ lzcol,
    float* __restrict__ pm, float* __restrict__ pZ)
{
    const float*  Af = (const float*)Av;
    const __half* Ah = (const __half*)Av;
    const float*  Bf = (const float*)Bv;
    const __half* Bh = (const __half*)Bv;
    float*  Cf = (float*)Cv;
    __half* Ch = (__half*)Cv;

    __shared__ __align__(16) __half Asm[2][128 * SSTR];
    __shared__ __align__(16) __half Bsm[2][128 * SSTR];
    __shared__ float2 statS[STATS ? 128 : 1][2];

    const int tid  = threadIdx.x;
    const int lane = tid & 31;
    const int wid  = tid >> 5;          // 0..3
    const int wm   = wid >> 1;          // 0..1 -> 64 rows
    const int wn   = wid & 1;           // 0..1 -> 64 cols
    const int row0 = blockIdx.y * 128;
    const int col0 = blockIdx.x * 128;
    const int koff = blockIdx.z * K;

    // f32 staging map (128 thr): 16 rows/pass, 8 passes
    const int a_r = tid >> 3;           // 0..15
    const int a_c = (tid & 7) * 4;
    // f16 staging map (128 thr): 32 rows/pass, 4 passes
    const int h_r = tid >> 2;           // 0..31
    const int h_c = (tid & 3) * 8;

    float acc[4][8][4];
#pragma unroll
    for (int i = 0; i < 4; i++)
#pragma unroll
        for (int j = 0; j < 8; j++)
#pragma unroll
            for (int r = 0; r < 4; r++) acc[i][j][r] = 0.0f;

    uint2 aF[8], bF[8];
    uint4 aH[4], bH[4];

    auto ldg_tile = [&](int k0) {
        if (AH) {
#pragma unroll
            for (int l = 0; l < 4; l++) {
                int r = h_r + 32 * l;
                uint4 v = *reinterpret_cast<const uint4*>(
                    &Ah[(size_t)(row0 + r) * lda + koff + k0 + h_c]);
                if (EXP_A) {
                    float4 l0 = *reinterpret_cast<const float4*>(&lzcol[koff + k0 + h_c]);
                    float4 l1 = *reinterpret_cast<const float4*>(&lzcol[koff + k0 + h_c + 4]);
                    __half2* p = reinterpret_cast<__half2*>(&v);
                    float2 f;
                    f = __half22float2(p[0]);
                    p[0] = __floats2half2_rn(__expf(f.x - l0.x), __expf(f.y - l0.y));
                    f = __half22float2(p[1]);
                    p[1] = __floats2half2_rn(__expf(f.x - l0.z), __expf(f.y - l0.w));
                    f = __half22float2(p[2]);
                    p[2] = __floats2half2_rn(__expf(f.x - l1.x), __expf(f.y - l1.y));
                    f = __half22float2(p[3]);
                    p[3] = __floats2half2_rn(__expf(f.x - l1.z), __expf(f.y - l1.w));
                }
                aH[l] = v;
            }
        } else {
#pragma unroll
            for (int l = 0; l < 8; l++) {
                int r = a_r + 16 * l;
                aF[l] = pack_f4(*reinterpret_cast<const float4*>(
                    &Af[(size_t)(row0 + r) * lda + koff + k0 + a_c]));
            }
        }
        if (BH) {
#pragma unroll
            for (int l = 0; l < 4; l++) {
                int r = h_r + 32 * l;
                bH[l] = *reinterpret_cast<const uint4*>(
                    &Bh[(size_t)(col0 + r) * ldb + koff + k0 + h_c]);
            }
        } else {
#pragma unroll
            for (int l = 0; l < 8; l++) {
                int r = a_r + 16 * l;
                bF[l] = pack_f4(*reinterpret_cast<const float4*>(
                    &Bf[(size_t)(col0 + r) * ldb + koff + k0 + a_c]));
            }
        }
    };

    auto sts_tile = [&](int s) {
        if (AH) {
#pragma unroll
            for (int l = 0; l < 4; l++) {
                int r = h_r + 32 * l;
                *reinterpret_cast<uint4*>(&Asm[s][r * SSTR + h_c]) = aH[l];
            }
        } else {
#pragma unroll
            for (int l = 0; l < 8; l++) {
                int r = a_r + 16 * l;
                *reinterpret_cast<uint2*>(&Asm[s][r * SSTR + a_c]) = aF[l];
            }
        }
        if (BH) {
#pragma unroll
            for (int l = 0; l < 4; l++) {
                int r = h_r + 32 * l;
                *reinterpret_cast<uint4*>(&Bsm[s][r * SSTR + h_c]) = bH[l];
            }
        } else {
#pragma unroll
            for (int l = 0; l < 8; l++) {
                int r = a_r + 16 * l;
                *reinterpret_cast<uint2*>(&Bsm[s][r * SSTR + a_c]) = bF[l];
            }
        }
    };

    const int grp = lane >> 3;
    const int wi  = lane & 7;

    auto compute = [&](int s) {
        const uint32_t sa  = smem_u32(&Asm[s][0]);
        const uint32_t sbm = smem_u32(&Bsm[s][0]);
#pragma unroll
        for (int ks = 0; ks < 2; ks++) {
            uint32_t af[4][4], bf[8][2];
#pragma unroll
            for (int mt = 0; mt < 4; mt++) {
                int r  = wm * 64 + mt * 16 + (grp & 1) * 8 + wi;
                int kh = ks * 16 + (grp >> 1) * 8;
                LDSM_X4(af[mt][0], af[mt][1], af[mt][2], af[mt][3],
                        sa + (uint32_t)(r * (SSTR * 2) + kh * 2));
            }
#pragma unroll
            for (int hb = 0; hb < 4; hb++) {
                int r  = wn * 64 + hb * 16 + (grp >> 1) * 8 + wi;
                int kh = ks * 16 + (grp & 1) * 8;
                LDSM_X4(bf[2 * hb][0], bf[2 * hb][1],
                        bf[2 * hb + 1][0], bf[2 * hb + 1][1],
                        sbm + (uint32_t)(r * (SSTR * 2) + kh * 2));
            }
#pragma unroll
            for (int mt = 0; mt < 4; mt++)
#pragma unroll
                for (int nt = 0; nt < 8; nt++)
                    MMA_16816(acc[mt][nt], af[mt], bf[nt]);
        }
    };

    ldg_tile(0);
    sts_tile(0);
    __syncthreads();

    const int niter = K / 32;
    for (int it = 0; it < niter; it++) {
        int cur = it & 1;
        if (it + 1 < niter) ldg_tile((it + 1) * 32);
        compute(cur);
        if (it + 1 < niter) {
            sts_tile(cur ^ 1);
            __syncthreads();
        }
    }

    // ---- epilogue ----
    const int g  = lane >> 2;
    const int tg = lane & 3;
    const int rbase = row0 + wm * 64;
    const int cbase = col0 + wn * 64;
#pragma unroll
    for (int mt = 0; mt < 4; mt++)
#pragma unroll
        for (int nt = 0; nt < 8; nt++)
#pragma unroll
            for (int hh = 0; hh < 2; hh++) {
                int r = rbase + mt * 16 + g + 8 * hh;
                int c = cbase + nt * 8 + 2 * tg;
                float o0 = acc[mt][nt][2 * hh + 0];
                float o1 = acc[mt][nt][2 * hh + 1];
                size_t base = (size_t)r * N + c;
                if (MODE == 0 || MODE == 1) {
                    if (MODE == 0) { o0 += bias[c]; o1 += bias[c + 1]; }
                    else           { o0 *= scale;  o1 *= scale; }
                    if (CH) {
                        *reinterpret_cast<__half2*>(&Ch[base]) =
                            __floats2half2_rn(o0, o1);
                    } else {
                        *reinterpret_cast<float2*>(&Cf[base]) = make_float2(o0, o1);
                    }
                } else {
                    atomicAdd(&Cf[base],     o0);
                    atomicAdd(&Cf[base + 1], o1);
                }
            }

    if (STATS) {
#pragma unroll
        for (int nt = 0; nt < 8; nt++)
#pragma unroll
            for (int j = 0; j < 2; j++) {
                float m = -INFINITY;
#pragma unroll
                for (int mt = 0; mt < 4; mt++)
#pragma unroll
                    for (int hh = 0; hh < 2; hh++)
                        m = fmaxf(m, acc[mt][nt][2 * hh + j] * scale);
                float s = 0.0f;
#pragma unroll
                for (int mt = 0; mt < 4; mt++)
#pragma unroll
                    for (int hh = 0; hh < 2; hh++)
                        s += __expf(acc[mt][nt][2 * hh + j] * scale - m);
#pragma unroll
                for (int msk = 4; msk <= 16; msk <<= 1) {
                    float om = __shfl_xor_sync(0xffffffffu, m, msk);
                    float os = __shfl_xor_sync(0xffffffffu, s, msk);
                    float nm = fmaxf(m, om);
                    s = s * __expf(m - nm) + os * __expf(om - nm);
                    m = nm;
                }
                if (g == 0) {
                    int c = wn * 64 + nt * 8 + 2 * tg + j;
                    statS[c][wm] = make_float2(m, s);
                }
            }
        __syncthreads();
        {
            float2 s0 = statS[tid][0];
            float2 s1 = statS[tid][1];
            float nm = fmaxf(s0.x, s1.x);
            float ss = s0.y * __expf(s0.x - nm) + s1.y * __expf(s1.x - nm);
            pm[(size_t)blockIdx.y * N_TOK + col0 + tid] = nm;
            pZ[(size_t)blockIdx.y * N_TOK + col0 + tid] = ss;
        }
    }
}

// ---------------------------------------------------------------------------
// prep: all 5 weight transposes (f32 -> fp16 NT) + bias concat, one launch.
// grid = 387 blocks of 256 threads.
// ---------------------------------------------------------------------------
__global__ __launch_bounds__(256) void prep_kernel(
    const float* __restrict__ W1, const float* __restrict__ Wq,
    const float* __restrict__ Wk, const float* __restrict__ Wv,
    const float* __restrict__ W2, const float* __restrict__ bq,
    const float* __restrict__ bk, const float* __restrict__ bv)
{
    const int id  = blockIdx.x;
    const int tid = threadIdx.x;
    if (id >= 384) {
        int i = (id - 384) * 256 + tid;   // 0..767
        g_bqkv[i] = (i < 256) ? bq[i] : (i < 512) ? bk[i - 256] : bv[i - 512];
        return;
    }
    const float* in;
    __half* out;
    int R, Cc, tile;
    if (id < 128)      { in = W1; out = g_W1t;               R = D_IN; Cc = HID;   tile = id; }
    else if (id < 192) { in = Wq; out = g_Wqkvt;             R = HID;  Cc = HID;   tile = id - 128; }
    else if (id < 256) { in = Wk; out = g_Wqkvt + HID * HID; R = HID;  Cc = HID;   tile = id - 192; }
    else if (id < 320) { in = Wv; out = g_Wqkvt + 2 * HID * HID; R = HID; Cc = HID; tile = id - 256; }
    else               { in = W2; out = g_W2t;               R = HID;  Cc = C_OUT; tile = id - 320; }
    int ntx = Cc / 32;
    int c0 = (tile % ntx) * 32, r0 = (tile / ntx) * 32;
    __shared__ float t[32][33];
    int tx = tid & 31, ty = tid >> 5;
#pragma unroll
    for (int i = ty; i < 32; i += 8)
        t[i][tx] = in[(size_t)(r0 + i) * Cc + c0 + tx];
    __syncthreads();
#pragma unroll
    for (int i = ty; i < 32; i += 8)
        out[(size_t)(c0 + i) * R + r0 + tx] = __float2half(t[tx][i]);
}

// ---------------------------------------------------------------------------
// vT[n][j] = qkv[j][512+n]*(1-a)  (blocks 0..2047)  +  h2 = a*h (2048..3071)
// ---------------------------------------------------------------------------
__global__ __launch_bounds__(256) void vprime_init_kernel(const float* __restrict__ aptr)
{
    const int id  = blockIdx.x;
    const int tid = threadIdx.x;
    if (id < 2048) {
        int n0 = (id & 7) * 32, j0 = (id >> 3) * 32;
        float av = 1.0f - *aptr;
        __shared__ float t[32][33];
        int tx = tid & 31, ty = tid >> 5;
#pragma unroll
        for (int i = ty; i < 32; i += 8)
            t[i][tx] = __half2float(
                g_qkv[(size_t)(j0 + i) * 768 + 512 + n0 + tx]) * av;
        __syncthreads();
#pragma unroll
        for (int i = ty; i < 32; i += 8)
            g_vT[(size_t)(n0 + i) * N_TOK + j0 + tx] = __float2half(t[tx][i]);
    } else {
        float av = *aptr;
        size_t base = ((size_t)(id - 2048) * 256 + tid) * 8;
        uint4 v = *reinterpret_cast<const uint4*>(&g_h[base]);
        const __half2* p = reinterpret_cast<const __half2*>(&v);
        float4 o0, o1;
        float2 f;
        f = __half22float2(p[0]); o0.x = av * f.x; o0.y = av * f.y;
        f = __half22float2(p[1]); o0.z = av * f.x; o0.w = av * f.y;
        f = __half22float2(p[2]); o1.x = av * f.x; o1.y = av * f.y;
        f = __half22float2(p[3]); o1.z = av * f.x; o1.w = av * f.y;
        *reinterpret_cast<float4*>(&g_h2[base])     = o0;
        *reinterpret_cast<float4*>(&g_h2[base + 4]) = o1;
    }
}

// combine 64 per-rowblock partials -> LZ[j] = m + ln Z
__global__ __launch_bounds__(256) void colstats_combine()
{
    int j = blockIdx.x * 256 + threadIdx.x;
    float mx = -INFINITY, s = 0.0f;
#pragma unroll 8
    for (int c = 0; c < NCHUNK; c++) {
        float mc = g_pm[(size_t)c * N_TOK + j];
        float zc = g_pZ[(size_t)c * N_TOK + j];
        float mn = fmaxf(mx, mc);
        s  = s * __expf(mx - mn) + zc * __expf(mc - mn);
        mx = mn;
    }
    g_LZ[j] = mx + logf(s);
}

// ---------------------------------------------------------------------------
extern "C" void kernel_launch(void* const* d_in, const int* in_sizes, int n_in,
                              void* d_out, int out_size)
{
    const float* x  = (const float*)d_in[0];
    const float* W1 = (const float*)d_in[1];
    const float* b1 = (const float*)d_in[2];
    const float* Wq = (const float*)d_in[3];
    const float* bq = (const float*)d_in[4];
    const float* Wk = (const float*)d_in[5];
    const float* bk = (const float*)d_in[6];
    const float* Wv = (const float*)d_in[7];
    const float* bv = (const float*)d_in[8];
    const float* a  = (const float*)d_in[9];
    const float* W2 = (const float*)d_in[10];
    const float* b2 = (const float*)d_in[11];
    float* out = (float*)d_out;

    __half *h, *qkv, *S, *vT, *W1t, *Wqkvt, *W2t;
    float *h2, *LZ, *pm, *pZ, *bqkv;
    cudaGetSymbolAddress((void**)&h,     g_h);
    cudaGetSymbolAddress((void**)&qkv,   g_qkv);
    cudaGetSymbolAddress((void**)&h2,    g_h2);
    cudaGetSymbolAddress((void**)&S,     g_S);
    cudaGetSymbolAddress((void**)&LZ,    g_LZ);
    cudaGetSymbolAddress((void**)&pm,    g_pm);
    cudaGetSymbolAddress((void**)&pZ,    g_pZ);
    cudaGetSymbolAddress((void**)&W1t,   g_W1t);
    cudaGetSymbolAddress((void**)&Wqkvt, g_Wqkvt);
    cudaGetSymbolAddress((void**)&bqkv,  g_bqkv);
    cudaGetSymbolAddress((void**)&W2t,   g_W2t);
    cudaGetSymbolAddress((void**)&vT,    g_vT);

    const float scale = 0.0625f; // 1/sqrt(256)

    // 0) all weight transposes + bias concat (one launch)
    prep_kernel<<<387, 256>>>(W1, Wq, Wk, Wv, W2, bq, bk, bv);

    // 1) h = x @ W1 + b1          (A f32, B f16, C f16)
    hmma_gemm<0, false, false, false, true, true>
        <<<dim3(HID / 128, N_TOK / 128, 1), 128>>>(
        x, W1t, h, HID, D_IN, D_IN, D_IN, b1, 0.f, nullptr, nullptr, nullptr);
    // 2) qkv = h @ Wqkv + bqkv    (all f16)
    hmma_gemm<0, false, false, true, true, true>
        <<<dim3(768 / 128, N_TOK / 128, 1), 128>>>(
        h, Wqkvt, qkv, 768, HID, HID, HID, bqkv, 0.f, nullptr, nullptr, nullptr);
    // 3) vT = (v * (1-a))^T ; h2 = a*h   (one launch)
    vprime_init_kernel<<<3072, 256>>>(a);
    // 4) S = (q @ k^T) * scale, fused per-rowblock column stats (S f16)
    hmma_gemm<1, false, true, true, true, true>
        <<<dim3(N_TOK / 128, N_TOK / 128, 1), 128>>>(
        qkv, qkv + HID, S, N_TOK, HID, 768, 768, nullptr, scale, nullptr, pm, pZ);
    // 5) combine stats -> LZ
    colstats_combine<<<N_TOK / 256, 256>>>();
    // 6) h2 += exp(S - LZ[col]) @ vT^T   (split-K=2, atomic f32 accumulate)
    hmma_gemm<3, true, false, true, true, false>
        <<<dim3(HID / 128, N_TOK / 128, 2), 128>>>(
        S, vT, h2, HID, N_TOK / 2, N_TOK, N_TOK, nullptr, 0.f, LZ, nullptr, nullptr);
    // 7) out = h2 @ W2 + b2       (A f32, B f16, C f32)
    hmma_gemm<0, false, false, false, true, false>
        <<<dim3(C_OUT / 128, N_TOK / 128, 1), 128>>>(
        h2, W2t, out, C_OUT, HID, HID, HID, b2, 0.f, nullptr, nullptr, nullptr);

    (void)in_sizes; (void)n_in; (void)out_size;
}